// round 10
// baseline (speedup 1.0000x reference)
#include <cuda_runtime.h>
#include <math.h>
#include <stdint.h>

#define Bz 8
#define Cc 3
#define IMGc 384
#define Pp 16
#define Gg 24
#define Dd 384
#define Hh 6
#define HD 64
#define Ll 12
#define MLPd 1536
#define NCLSc 1000
#define TMAX 577
#define NMAX 576
#define KTS 608
#define EPSc 1e-6f
#define LN_EPSc 1e-5f
#define GAMMAc 0.1f
#define MIN_TOK 16
#define QKVW (3*Dd)

// ---------------- device scratch ----------------
__device__ float g_x[Bz*TMAX*Dd];
__device__ float g_x2[Bz*TMAX*Dd];
__device__ float g_xn[Bz*TMAX*Dd];
__device__ float g_ao[Bz*TMAX*Dd];
__device__ float g_qkv[Bz*TMAX*QKVW];
__device__ float g_ktr[Bz*Hh*HD*KTS];
__device__ float g_h1[Bz*TMAX*MLPd];
__device__ float g_patches[Bz*NMAX*Cc*Pp*Pp];
__device__ float g_attn_cls[Bz*Hh*TMAX];
__device__ float g_vnorm[Bz*Hh*TMAX];
__device__ float g_ent[Bz*Hh];
__device__ float g_raw[Bz*TMAX];
__device__ float g_mass[Bz];
__device__ float g_prevmass[Bz];
__device__ float g_scores[NMAX];
__device__ int   g_keep[TMAX];
__device__ float g_cls[Bz*Dd];
__device__ int g_T, g_Tnew, g_prev_valid;

// ---------------- init ----------------
__global__ void init_k(const float* __restrict__ cls_token, const float* __restrict__ pos) {
    int b = blockIdx.x, d = threadIdx.x;
    g_x[((size_t)b*TMAX)*Dd + d] = cls_token[d] + pos[d];
    if (b == 0 && d == 0) { g_T = TMAX; g_prev_valid = 0; }
}

// ---------------- patch extraction ----------------
__global__ void patchify_k(const float* __restrict__ x) {
    int idx = blockIdx.x*blockDim.x + threadIdx.x;
    if (idx >= Bz*NMAX*(Cc*Pp*Pp)) return;
    int k = idx % (Cc*Pp*Pp);
    int g = (idx/(Cc*Pp*Pp)) % NMAX;
    int b = idx/((Cc*Pp*Pp)*NMAX);
    int px = k & 15, py = (k>>4)&15, c = k>>8;
    int gx = g % Gg, gy = g / Gg;
    g_patches[idx] = x[(((size_t)b*Cc + c)*IMGc + gy*Pp+py)*IMGc + gx*Pp+px];
}

// ---------------- tiled fp32 GEMM: 64x64 tile, 128 threads, 8x4 microtile ----
// (proven R2 kernel — untouched)
__global__ void __launch_bounds__(128) gemm_k(
    const float* __restrict__ A, const float* __restrict__ W,
    const float* __restrict__ bias, float* __restrict__ C,
    const float* __restrict__ resid, const float* __restrict__ posadd,
    int K, int N, int Astride, int Cstride, int rowoff, int fixedT, int act)
{
    int T = fixedT ? fixedT : g_T;
    int t0 = blockIdx.x * 64;
    if (t0 >= T) return;
    int n0 = blockIdx.y * 64;
    int b  = blockIdx.z;
    const float* Ab = A + (size_t)b * Astride * K;

    __shared__ float As[16][64];
    __shared__ float Ws[16][64];

    int tid = threadIdx.x;
    int tx = tid & 15, ty = tid >> 4;
    int arow = tid >> 2, aq = tid & 3;
    int wrow = tid >> 4, wq = tid & 15;

    float acc[8][4];
#pragma unroll
    for (int i=0;i<8;i++)
#pragma unroll
        for (int j=0;j<4;j++) acc[i][j]=0.f;

    for (int k0 = 0; k0 < K; k0 += 16) {
        {
            int t = t0 + arow;
            float4 v = make_float4(0.f,0.f,0.f,0.f);
            if (t < T) v = *reinterpret_cast<const float4*>(Ab + (size_t)t*K + k0 + aq*4);
            As[aq*4+0][arow]=v.x; As[aq*4+1][arow]=v.y; As[aq*4+2][arow]=v.z; As[aq*4+3][arow]=v.w;
            t = t0 + arow + 32;
            v = make_float4(0.f,0.f,0.f,0.f);
            if (t < T) v = *reinterpret_cast<const float4*>(Ab + (size_t)t*K + k0 + aq*4);
            As[aq*4+0][arow+32]=v.x; As[aq*4+1][arow+32]=v.y; As[aq*4+2][arow+32]=v.z; As[aq*4+3][arow+32]=v.w;
        }
        *reinterpret_cast<float4*>(&Ws[wrow][wq*4])   = *reinterpret_cast<const float4*>(W + (size_t)(k0+wrow)*N   + n0 + wq*4);
        *reinterpret_cast<float4*>(&Ws[wrow+8][wq*4]) = *reinterpret_cast<const float4*>(W + (size_t)(k0+wrow+8)*N + n0 + wq*4);
        __syncthreads();
#pragma unroll
        for (int kk = 0; kk < 16; kk++) {
            float4 wv = *reinterpret_cast<const float4*>(&Ws[kk][tx*4]);
            float4 a0 = *reinterpret_cast<const float4*>(&As[kk][ty*8]);
            float4 a1 = *reinterpret_cast<const float4*>(&As[kk][ty*8+4]);
            acc[0][0]+=a0.x*wv.x; acc[0][1]+=a0.x*wv.y; acc[0][2]+=a0.x*wv.z; acc[0][3]+=a0.x*wv.w;
            acc[1][0]+=a0.y*wv.x; acc[1][1]+=a0.y*wv.y; acc[1][2]+=a0.y*wv.z; acc[1][3]+=a0.y*wv.w;
            acc[2][0]+=a0.z*wv.x; acc[2][1]+=a0.z*wv.y; acc[2][2]+=a0.z*wv.z; acc[2][3]+=a0.z*wv.w;
            acc[3][0]+=a0.w*wv.x; acc[3][1]+=a0.w*wv.y; acc[3][2]+=a0.w*wv.z; acc[3][3]+=a0.w*wv.w;
            acc[4][0]+=a1.x*wv.x; acc[4][1]+=a1.x*wv.y; acc[4][2]+=a1.x*wv.z; acc[4][3]+=a1.x*wv.w;
            acc[5][0]+=a1.y*wv.x; acc[5][1]+=a1.y*wv.y; acc[5][2]+=a1.y*wv.z; acc[5][3]+=a1.y*wv.w;
            acc[6][0]+=a1.z*wv.x; acc[6][1]+=a1.z*wv.y; acc[6][2]+=a1.z*wv.z; acc[6][3]+=a1.z*wv.w;
            acc[7][0]+=a1.w*wv.x; acc[7][1]+=a1.w*wv.y; acc[7][2]+=a1.w*wv.z; acc[7][3]+=a1.w*wv.w;
        }
        __syncthreads();
    }

    float4 bv = *reinterpret_cast<const float4*>(&bias[n0 + tx*4]);
#pragma unroll
    for (int i = 0; i < 8; i++) {
        int t = t0 + ty*8 + i;
        if (t >= T) continue;
        float4 v;
        v.x = acc[i][0]+bv.x; v.y = acc[i][1]+bv.y; v.z = acc[i][2]+bv.z; v.w = acc[i][3]+bv.w;
        if (act) {
            v.x = 0.5f*v.x*(1.0f + erff(v.x*0.70710678118654752f));
            v.y = 0.5f*v.y*(1.0f + erff(v.y*0.70710678118654752f));
            v.z = 0.5f*v.z*(1.0f + erff(v.z*0.70710678118654752f));
            v.w = 0.5f*v.w*(1.0f + erff(v.w*0.70710678118654752f));
        }
        size_t co = ((size_t)b*Cstride + rowoff + t)*(size_t)N + n0 + tx*4;
        if (resid) {
            float4 r = *reinterpret_cast<const float4*>(&resid[co]);
            v.x+=r.x; v.y+=r.y; v.z+=r.z; v.w+=r.w;
        }
        if (posadd) {
            float4 p = *reinterpret_cast<const float4*>(&posadd[(size_t)(rowoff+t)*N + n0 + tx*4]);
            v.x+=p.x; v.y+=p.y; v.z+=p.z; v.w+=p.w;
        }
        *reinterpret_cast<float4*>(&C[co]) = v;
    }
}

// ---------------- K transpose + V norms fused ----------------
__global__ void __launch_bounds__(256) transp_k() {
    int T = g_T;
    int t0 = blockIdx.x * 32;
    if (t0 >= T) return;
    int bh = blockIdx.y;
    int b = bh / Hh, h = bh % Hh;
    int tid = threadIdx.x;
    __shared__ float tile[64][33];

    const float* base = g_qkv + (size_t)b*TMAX*QKVW + Dd + h*HD;
#pragma unroll
    for (int i = 0; i < 8; i++) {
        int idx = i*256 + tid;
        int r = idx >> 6, c = idx & 63;
        int t = t0 + r;
        float v = (t < T) ? base[(size_t)t*QKVW + c] : 0.f;
        tile[c][r] = v;
    }
    __syncthreads();
    float* kout = g_ktr + (size_t)bh*HD*KTS;
#pragma unroll
    for (int i = 0; i < 8; i++) {
        int idx = i*256 + tid;
        int dd = idx >> 5, tt = idx & 31;
        kout[(size_t)dd*KTS + t0 + tt] = tile[dd][tt];
    }

    // fused V norms: 8 warps x 4 tokens each
    int w = tid >> 5, lane = tid & 31;
    const float* vbase = g_qkv + (size_t)b*TMAX*QKVW + 2*Dd + h*HD;
#pragma unroll
    for (int j = 0; j < 4; j++) {
        int t = t0 + w*4 + j;
        if (t < T) {
            const float* v = vbase + (size_t)t*QKVW;
            float s = v[lane]*v[lane] + v[lane+32]*v[lane+32];
#pragma unroll
            for (int o=16;o;o>>=1) s += __shfl_xor_sync(0xffffffffu, s, o);
            if (!lane) g_vnorm[bh*TMAX + t] = sqrtf(s);
        }
    }
}

// ---------------- layernorm: warp per row ----------------
__global__ void ln_k(const float* __restrict__ in, float* __restrict__ out,
                     const float* __restrict__ sc, const float* __restrict__ bi,
                     int inStride, int outStride, int fixedT)
{
    int T = fixedT ? fixedT : g_T;
    int lane = threadIdx.x & 31, w = threadIdx.x >> 5;
    int t = blockIdx.x*4 + w;
    if (t >= T) return;
    int b = blockIdx.y;
    const float4* row = reinterpret_cast<const float4*>(in + ((size_t)b*inStride + t)*Dd);
    float4 v0=row[lane], v1=row[lane+32], v2=row[lane+64];
    float s = v0.x+v0.y+v0.z+v0.w + v1.x+v1.y+v1.z+v1.w + v2.x+v2.y+v2.z+v2.w;
#pragma unroll
    for (int o=16;o;o>>=1) s += __shfl_xor_sync(0xffffffffu, s, o);
    float mean = s*(1.0f/Dd);
    float4 d0,d1,d2;
    d0.x=v0.x-mean; d0.y=v0.y-mean; d0.z=v0.z-mean; d0.w=v0.w-mean;
    d1.x=v1.x-mean; d1.y=v1.y-mean; d1.z=v1.z-mean; d1.w=v1.w-mean;
    d2.x=v2.x-mean; d2.y=v2.y-mean; d2.z=v2.z-mean; d2.w=v2.w-mean;
    float q = d0.x*d0.x+d0.y*d0.y+d0.z*d0.z+d0.w*d0.w
            + d1.x*d1.x+d1.y*d1.y+d1.z*d1.z+d1.w*d1.w
            + d2.x*d2.x+d2.y*d2.y+d2.z*d2.z+d2.w*d2.w;
#pragma unroll
    for (int o=16;o;o>>=1) q += __shfl_xor_sync(0xffffffffu, q, o);
    float inv = 1.0f/sqrtf(q*(1.0f/Dd) + LN_EPSc);
    const float4* sc4 = reinterpret_cast<const float4*>(sc);
    const float4* bi4 = reinterpret_cast<const float4*>(bi);
    float4* orow = reinterpret_cast<float4*>(out + ((size_t)b*outStride + t)*Dd);
    float4 s0=sc4[lane], s1=sc4[lane+32], s2=sc4[lane+64];
    float4 b0=bi4[lane], b1=bi4[lane+32], b2=bi4[lane+64];
    float4 o0,o1,o2;
    o0.x=d0.x*inv*s0.x+b0.x; o0.y=d0.y*inv*s0.y+b0.y; o0.z=d0.z*inv*s0.z+b0.z; o0.w=d0.w*inv*s0.w+b0.w;
    o1.x=d1.x*inv*s1.x+b1.x; o1.y=d1.y*inv*s1.y+b1.y; o1.z=d1.z*inv*s1.z+b1.z; o1.w=d1.w*inv*s1.w+b1.w;
    o2.x=d2.x*inv*s2.x+b2.x; o2.y=d2.y*inv*s2.y+b2.y; o2.z=d2.z*inv*s2.z+b2.z; o2.w=d2.w*inv*s2.w+b2.w;
    orow[lane]=o0; orow[lane+32]=o1; orow[lane+64]=o2;
}

// ---------------- attention: 16 queries per block, 256 threads ----------------
__global__ void __launch_bounds__(256) attn_k() {
    int T = g_T;
    int q0 = blockIdx.x * 16;
    if (q0 >= T) return;
    int bh = blockIdx.y;
    int b = bh / Hh, h = bh % Hh;
    int tid = threadIdx.x;

    __shared__ float sqT[HD][16];
    __shared__ float sc[16][TMAX];
    __shared__ float redsm[16][64];

    const float* base = g_qkv + (size_t)b*TMAX*QKVW;

    // load 16 q rows transposed: sqT[d][q]
    for (int e = tid; e < 16*HD; e += 256) {
        int q = e >> 6, d = e & 63;
        float v = 0.f;
        if (q0+q < T) v = base[(size_t)(q0+q)*QKVW + h*HD + d];
        sqT[d][q] = v;
    }
    __syncthreads();

    // scores: thread per key, coalesced K^T reads, ascending-d accumulation
    const float* kt = g_ktr + (size_t)bh*HD*KTS;
    for (int k = tid; k < T; k += 256) {
        float acc[16];
#pragma unroll
        for (int q=0;q<16;q++) acc[q]=0.f;
        const float* kp = kt + k;
#pragma unroll 4
        for (int d = 0; d < HD; d++) {
            float kv = kp[(size_t)d*KTS];
            float4 qa = *reinterpret_cast<const float4*>(&sqT[d][0]);
            float4 qb = *reinterpret_cast<const float4*>(&sqT[d][4]);
            float4 qc = *reinterpret_cast<const float4*>(&sqT[d][8]);
            float4 qd = *reinterpret_cast<const float4*>(&sqT[d][12]);
            acc[0]  += kv*qa.x; acc[1]  += kv*qa.y; acc[2]  += kv*qa.z; acc[3]  += kv*qa.w;
            acc[4]  += kv*qb.x; acc[5]  += kv*qb.y; acc[6]  += kv*qb.z; acc[7]  += kv*qb.w;
            acc[8]  += kv*qc.x; acc[9]  += kv*qc.y; acc[10] += kv*qc.z; acc[11] += kv*qc.w;
            acc[12] += kv*qd.x; acc[13] += kv*qd.y; acc[14] += kv*qd.z; acc[15] += kv*qd.w;
        }
#pragma unroll
        for (int q = 0; q < 16; q++) sc[q][k] = acc[q]*0.125f;
    }
    __syncthreads();

    // softmax: warp w handles queries 2w and 2w+1
    {
        int w = tid >> 5, lane = tid & 31;
#pragma unroll
        for (int half = 0; half < 2; half++) {
            int q = w*2 + half;
            float m = -3.4e38f;
            for (int k=lane; k<T; k+=32) m = fmaxf(m, sc[q][k]);
#pragma unroll
            for (int o=16;o;o>>=1) m = fmaxf(m, __shfl_xor_sync(0xffffffffu, m, o));
            float s = 0.f;
            for (int k=lane; k<T; k+=32) { float e = expf(sc[q][k]-m); sc[q][k]=e; s+=e; }
#pragma unroll
            for (int o=16;o;o>>=1) s += __shfl_xor_sync(0xffffffffu, s, o);
            float inv = 1.0f/s;
            bool is_cls = (q0 + q == 0);
            for (int k=lane; k<T; k+=32) {
                float p = sc[q][k]*inv; sc[q][k]=p;
                if (is_cls) g_attn_cls[bh*TMAX + k] = p;
            }
        }
    }
    __syncthreads();

    // AV: 16 segments x 16 d-groups, 16 float4 accumulators
    int seg = tid >> 4, d4 = tid & 15;
    float4 a[16];
#pragma unroll
    for (int q=0;q<16;q++) a[q] = make_float4(0.f,0.f,0.f,0.f);
    for (int k = seg; k < T; k += 16) {
        float4 vv = *reinterpret_cast<const float4*>(base + (size_t)k*QKVW + 2*Dd + h*HD + d4*4);
#pragma unroll
        for (int q=0;q<16;q++) {
            float p = sc[q][k];
            a[q].x += p*vv.x; a[q].y += p*vv.y; a[q].z += p*vv.z; a[q].w += p*vv.w;
        }
    }
#pragma unroll
    for (int q=0;q<16;q++) {
        *reinterpret_cast<float4*>(&redsm[seg][d4*4]) = a[q];
        __syncthreads();
        if (tid < 64 && q0+q < T) {
            float s = 0.f;
#pragma unroll
            for (int sgi=0;sgi<16;sgi++) s += redsm[sgi][tid];
            g_ao[((size_t)b*TMAX + q0+q)*Dd + h*HD + tid] = s;
        }
        __syncthreads();
    }
}

// ---------------- per-batch stats ----------------
__global__ void stats_k() {
    int b = blockIdx.x, tid = threadIdx.x, T = g_T;
    __shared__ float red[256];
    for (int h = 0; h < Hh; h++) {
        float s = 0.f;
        for (int t = tid; t < T; t += 256) {
            float c = g_attn_cls[(b*Hh+h)*TMAX + t];
            s += c*logf(c + EPSc);
        }
        red[tid]=s; __syncthreads();
        for (int o=128;o;o>>=1){ if(tid<o) red[tid]+=red[tid+o]; __syncthreads(); }
        if (!tid) g_ent[b*Hh+h] = -red[0];
        __syncthreads();
    }
    int N = T-1;
    float loc = 0.f;
    for (int t=tid; t<N; t+=256) {
        float r = 0.f;
#pragma unroll
        for (int h=0;h<Hh;h++) {
            int o = (b*Hh+h)*TMAX + t+1;
            r += g_attn_cls[o]*g_vnorm[o];
        }
        g_raw[b*TMAX+t] = r; loc += r;
    }
    red[tid]=loc; __syncthreads();
    for (int o=128;o;o>>=1){ if(tid<o) red[tid]+=red[tid+o]; __syncthreads(); }
    if (!tid) g_mass[b] = red[0];
}

// ---------------- scores + decision + top-k selection ----------------
__global__ void keepsel_k() {
    int tid = threadIdx.x;
    int T = g_T, N = T-1;
    __shared__ float ssc[NMAX];
    __shared__ int sh_prune, sh_Nn;
    if (tid < N) {
        float s = 0.f;
#pragma unroll
        for (int b=0;b<Bz;b++) s += g_raw[b*TMAX+tid]/(g_mass[b]+EPSc);
        float sm = s*(1.0f/Bz);
        ssc[tid] = sm;
        g_scores[tid] = sm;
    }
    if (tid == 0) {
        int Nn = N, prune = 0;
        if (N > MIN_TOK) {
            float logT = logf((float)T);
            float rho_sum = 0.f;
            for (int b=0;b<Bz;b++) {
                float rb = 0.f;
                for (int h=0;h<Hh;h++) rb += g_ent[b*Hh+h]/logT;
                rho_sum += rb/(float)Hh;
            }
            float rho_mean = rho_sum/(float)Bz;
            if (g_prev_valid) {
                float ds = 0.f;
                for (int b=0;b<Bz;b++) ds += fabsf(g_mass[b]-g_prevmass[b])/(g_prevmass[b]+EPSc);
                float dm = ds/(float)Bz;
                float kr = 1.0f - GAMMAc*(rho_mean + dm);
                kr = fminf(fmaxf(kr, 0.0f), 1.0f);
                int cand = (int)((double)N*(double)kr);
                Nn = cand > MIN_TOK ? cand : MIN_TOK;
                if (Nn > N) Nn = N;
            }
            prune = (Nn < N) ? 1 : 0;
            for (int b=0;b<Bz;b++) g_prevmass[b] = g_mass[b];
            g_prev_valid = 1;
        }
        sh_prune = prune; sh_Nn = Nn;
        g_Tnew = Nn + 1;
    }
    __syncthreads();
    if (!sh_prune) {
        if (tid < T) g_keep[tid] = tid;
        return;
    }
    int Nn = sh_Nn;
    __shared__ unsigned char kept[NMAX];
    int isk = 0;
    if (tid < N) {
        float my = ssc[tid];
        int rank = 0;
        for (int j=0;j<N;j++) {
            float s = ssc[j];
            rank += (s > my) || (s == my && j < tid);
        }
        isk = (rank < Nn);
    }
    if (tid < NMAX) kept[tid] = (tid < N) ? (unsigned char)isk : 0;
    __syncthreads();
    if (tid < N && isk) {
        int pos = 1;
        for (int j=0;j<tid;j++) pos += kept[j];
        g_keep[pos] = tid + 1;
    }
    if (tid == 0) g_keep[0] = 0;
}

// ---------------- gather ----------------
__global__ void gather_k(const float* __restrict__ src, float* __restrict__ dst) {
    int pos = blockIdx.x;
    if (pos >= g_Tnew) return;
    int b = blockIdx.y;
    int s = g_keep[pos];
    const float4* sp = reinterpret_cast<const float4*>(src + ((size_t)b*TMAX + s)*Dd);
    float4* dp = reinterpret_cast<float4*>(dst + ((size_t)b*TMAX + pos)*Dd);
    if (threadIdx.x < 96) dp[threadIdx.x] = sp[threadIdx.x];
    if (pos==0 && b==0 && threadIdx.x==0) g_T = g_Tnew;
}

// ---------------- classifier head ----------------
__global__ void head_k(const float* __restrict__ hw, const float* __restrict__ hb,
                       float* __restrict__ out) {
    int b = blockIdx.y;
    __shared__ float xf[Dd];
    int tid = threadIdx.x;
    for (int d=tid; d<Dd; d+=256) xf[d] = g_cls[b*Dd+d];
    __syncthreads();
    int n = blockIdx.x*256 + tid;
    if (n < NCLSc) {
        float acc = hb[n];
        for (int k=0;k<Dd;k++) acc += xf[k]*hw[(size_t)k*NCLSc + n];
        out[(size_t)b*NCLSc + n] = acc;
    }
}

// ---------------- launch sequence ----------------
extern "C" void kernel_launch(void* const* d_in, const int* in_sizes, int n_in,
                              void* d_out, int out_size) {
    (void)in_sizes; (void)n_in; (void)out_size;
    const float* x        = (const float*)d_in[0];
    const float* patch_w  = (const float*)d_in[1];
    const float* patch_b  = (const float*)d_in[2];
    const float* cls_tok  = (const float*)d_in[3];
    const float* pos      = (const float*)d_in[4];
    const float* ln1_s    = (const float*)d_in[5];
    const float* ln1_b    = (const float*)d_in[6];
    const float* qkv_w    = (const float*)d_in[7];
    const float* qkv_b    = (const float*)d_in[8];
    const float* proj_w   = (const float*)d_in[9];
    const float* proj_b   = (const float*)d_in[10];
    const float* ln2_s    = (const float*)d_in[11];
    const float* ln2_b    = (const float*)d_in[12];
    const float* fc1_w    = (const float*)d_in[13];
    const float* fc1_b    = (const float*)d_in[14];
    const float* fc2_w    = (const float*)d_in[15];
    const float* fc2_b    = (const float*)d_in[16];
    const float* norm_s   = (const float*)d_in[17];
    const float* norm_b   = (const float*)d_in[18];
    const float* head_w   = (const float*)d_in[19];
    const float* head_b   = (const float*)d_in[20];
    float* out = (float*)d_out;

    float *pX,*pX2,*pXn,*pAo,*pQkv,*pH1,*pPat,*pCls;
    cudaGetSymbolAddress((void**)&pX,   g_x);
    cudaGetSymbolAddress((void**)&pX2,  g_x2);
    cudaGetSymbolAddress((void**)&pXn,  g_xn);
    cudaGetSymbolAddress((void**)&pAo,  g_ao);
    cudaGetSymbolAddress((void**)&pQkv, g_qkv);
    cudaGetSymbolAddress((void**)&pH1,  g_h1);
    cudaGetSymbolAddress((void**)&pPat, g_patches);
    cudaGetSymbolAddress((void**)&pCls, g_cls);

    init_k<<<Bz, Dd>>>(cls_tok, pos);
    {
        int tot = Bz*NMAX*Cc*Pp*Pp;
        patchify_k<<<(tot+255)/256, 256>>>(x);
    }
    gemm_k<<<dim3(9,6,Bz), 128>>>(pPat, patch_w, patch_b, pX, nullptr, pos,
                                  Cc*Pp*Pp, Dd, NMAX, TMAX, 1, NMAX, 0);

    float* bufs[2] = {pX, pX2};
    for (int l=0; l<Ll; l++) {
        float* cur = bufs[l & 1];
        float* nxt = bufs[(l+1) & 1];
        ln_k<<<dim3((TMAX+3)/4,Bz),128>>>(cur, pXn, ln1_s+l*Dd, ln1_b+l*Dd, TMAX, TMAX, 0);
        gemm_k<<<dim3(10,18,Bz), 128>>>(pXn, qkv_w + (size_t)l*Dd*QKVW, qkv_b + (size_t)l*QKVW,
                                        pQkv, nullptr, nullptr, Dd, QKVW, TMAX, TMAX, 0, 0, 0);
        transp_k<<<dim3((TMAX+31)/32, Bz*Hh), 256>>>();
        attn_k<<<dim3((TMAX+15)/16, Bz*Hh), 256>>>();
        gemm_k<<<dim3(10,6,Bz), 128>>>(pAo, proj_w + (size_t)l*Dd*Dd, proj_b + (size_t)l*Dd,
                                       cur, cur, nullptr, Dd, Dd, TMAX, TMAX, 0, 0, 0);
        ln_k<<<dim3((TMAX+3)/4,Bz),128>>>(cur, pXn, ln2_s+l*Dd, ln2_b+l*Dd, TMAX, TMAX, 0);
        gemm_k<<<dim3(10,24,Bz), 128>>>(pXn, fc1_w + (size_t)l*Dd*MLPd, fc1_b + (size_t)l*MLPd,
                                        pH1, nullptr, nullptr, Dd, MLPd, TMAX, TMAX, 0, 0, 1);
        gemm_k<<<dim3(10,6,Bz), 128>>>(pH1, fc2_w + (size_t)l*MLPd*Dd, fc2_b + (size_t)l*Dd,
                                       cur, cur, nullptr, MLPd, Dd, TMAX, TMAX, 0, 0, 0);
        stats_k<<<Bz, 256>>>();
        keepsel_k<<<1, 608>>>();
        gather_k<<<dim3(TMAX,Bz),128>>>(cur, nxt);
    }

    ln_k<<<dim3(1,Bz),128>>>(bufs[0], pCls, norm_s, norm_b, TMAX, 1, 1);
    head_k<<<dim3(4,Bz),256>>>(head_w, head_b, out);
}

// round 11
// speedup vs baseline: 1.0317x; 1.0317x over previous
#include <cuda_runtime.h>
#include <math.h>
#include <stdint.h>

#define Bz 8
#define Cc 3
#define IMGc 384
#define Pp 16
#define Gg 24
#define Dd 384
#define Hh 6
#define HD 64
#define Ll 12
#define MLPd 1536
#define NCLSc 1000
#define TMAX 577
#define NMAX 576
#define KTS 608
#define EPSc 1e-6f
#define LN_EPSc 1e-5f
#define GAMMAc 0.1f
#define MIN_TOK 16
#define QKVW (3*Dd)

// ---------------- device scratch ----------------
__device__ float g_x[Bz*TMAX*Dd];
__device__ float g_x2[Bz*TMAX*Dd];
__device__ float g_xn[Bz*TMAX*Dd];
__device__ float g_ao[Bz*TMAX*Dd];
__device__ float g_qkv[Bz*TMAX*QKVW];
__device__ float g_ktr[Bz*Hh*HD*KTS];
__device__ float g_h1[Bz*TMAX*MLPd];
__device__ float g_patches[Bz*NMAX*Cc*Pp*Pp];
__device__ float g_attn_cls[Bz*Hh*TMAX];
__device__ float g_vnorm[Bz*Hh*TMAX];
__device__ float g_ent[Bz*Hh];
__device__ float g_raw[Bz*TMAX];
__device__ float g_mass[Bz];
__device__ float g_prevmass[Bz];
__device__ float g_scores[NMAX];
__device__ int   g_keep[TMAX];
__device__ float g_cls[Bz*Dd];
__device__ int g_T, g_Tnew, g_prev_valid;

// ---------------- init ----------------
__global__ void init_k(const float* __restrict__ cls_token, const float* __restrict__ pos) {
    int b = blockIdx.x, d = threadIdx.x;
    g_x[((size_t)b*TMAX)*Dd + d] = cls_token[d] + pos[d];
    if (b == 0 && d == 0) { g_T = TMAX; g_prev_valid = 0; }
}

// ---------------- patch extraction ----------------
__global__ void patchify_k(const float* __restrict__ x) {
    int idx = blockIdx.x*blockDim.x + threadIdx.x;
    if (idx >= Bz*NMAX*(Cc*Pp*Pp)) return;
    int k = idx % (Cc*Pp*Pp);
    int g = (idx/(Cc*Pp*Pp)) % NMAX;
    int b = idx/((Cc*Pp*Pp)*NMAX);
    int px = k & 15, py = (k>>4)&15, c = k>>8;
    int gx = g % Gg, gy = g / Gg;
    g_patches[idx] = x[(((size_t)b*Cc + c)*IMGc + gy*Pp+py)*IMGc + gx*Pp+px];
}

// ---------------- tiled fp32 GEMM: 64x64 tile, 128 threads, 8x4 microtile ----
__global__ void __launch_bounds__(128) gemm_k(
    const float* __restrict__ A, const float* __restrict__ W,
    const float* __restrict__ bias, float* __restrict__ C,
    const float* __restrict__ resid, const float* __restrict__ posadd,
    int K, int N, int Astride, int Cstride, int rowoff, int fixedT, int act)
{
    int T = fixedT ? fixedT : g_T;
    int t0 = blockIdx.x * 64;
    if (t0 >= T) return;
    int n0 = blockIdx.y * 64;
    int b  = blockIdx.z;
    const float* Ab = A + (size_t)b * Astride * K;

    __shared__ float As[16][64];
    __shared__ float Ws[16][64];

    int tid = threadIdx.x;
    int tx = tid & 15, ty = tid >> 4;
    int arow = tid >> 2, aq = tid & 3;
    int wrow = tid >> 4, wq = tid & 15;

    float acc[8][4];
#pragma unroll
    for (int i=0;i<8;i++)
#pragma unroll
        for (int j=0;j<4;j++) acc[i][j]=0.f;

    for (int k0 = 0; k0 < K; k0 += 16) {
        {
            int t = t0 + arow;
            float4 v = make_float4(0.f,0.f,0.f,0.f);
            if (t < T) v = *reinterpret_cast<const float4*>(Ab + (size_t)t*K + k0 + aq*4);
            As[aq*4+0][arow]=v.x; As[aq*4+1][arow]=v.y; As[aq*4+2][arow]=v.z; As[aq*4+3][arow]=v.w;
            t = t0 + arow + 32;
            v = make_float4(0.f,0.f,0.f,0.f);
            if (t < T) v = *reinterpret_cast<const float4*>(Ab + (size_t)t*K + k0 + aq*4);
            As[aq*4+0][arow+32]=v.x; As[aq*4+1][arow+32]=v.y; As[aq*4+2][arow+32]=v.z; As[aq*4+3][arow+32]=v.w;
        }
        *reinterpret_cast<float4*>(&Ws[wrow][wq*4])   = *reinterpret_cast<const float4*>(W + (size_t)(k0+wrow)*N   + n0 + wq*4);
        *reinterpret_cast<float4*>(&Ws[wrow+8][wq*4]) = *reinterpret_cast<const float4*>(W + (size_t)(k0+wrow+8)*N + n0 + wq*4);
        __syncthreads();
#pragma unroll
        for (int kk = 0; kk < 16; kk++) {
            float4 wv = *reinterpret_cast<const float4*>(&Ws[kk][tx*4]);
            float4 a0 = *reinterpret_cast<const float4*>(&As[kk][ty*8]);
            float4 a1 = *reinterpret_cast<const float4*>(&As[kk][ty*8+4]);
            acc[0][0]+=a0.x*wv.x; acc[0][1]+=a0.x*wv.y; acc[0][2]+=a0.x*wv.z; acc[0][3]+=a0.x*wv.w;
            acc[1][0]+=a0.y*wv.x; acc[1][1]+=a0.y*wv.y; acc[1][2]+=a0.y*wv.z; acc[1][3]+=a0.y*wv.w;
            acc[2][0]+=a0.z*wv.x; acc[2][1]+=a0.z*wv.y; acc[2][2]+=a0.z*wv.z; acc[2][3]+=a0.z*wv.w;
            acc[3][0]+=a0.w*wv.x; acc[3][1]+=a0.w*wv.y; acc[3][2]+=a0.w*wv.z; acc[3][3]+=a0.w*wv.w;
            acc[4][0]+=a1.x*wv.x; acc[4][1]+=a1.x*wv.y; acc[4][2]+=a1.x*wv.z; acc[4][3]+=a1.x*wv.w;
            acc[5][0]+=a1.y*wv.x; acc[5][1]+=a1.y*wv.y; acc[5][2]+=a1.y*wv.z; acc[5][3]+=a1.y*wv.w;
            acc[6][0]+=a1.z*wv.x; acc[6][1]+=a1.z*wv.y; acc[6][2]+=a1.z*wv.z; acc[6][3]+=a1.z*wv.w;
            acc[7][0]+=a1.w*wv.x; acc[7][1]+=a1.w*wv.y; acc[7][2]+=a1.w*wv.z; acc[7][3]+=a1.w*wv.w;
        }
        __syncthreads();
    }

    float4 bv = *reinterpret_cast<const float4*>(&bias[n0 + tx*4]);
#pragma unroll
    for (int i = 0; i < 8; i++) {
        int t = t0 + ty*8 + i;
        if (t >= T) continue;
        float4 v;
        v.x = acc[i][0]+bv.x; v.y = acc[i][1]+bv.y; v.z = acc[i][2]+bv.z; v.w = acc[i][3]+bv.w;
        if (act) {
            v.x = 0.5f*v.x*(1.0f + erff(v.x*0.70710678118654752f));
            v.y = 0.5f*v.y*(1.0f + erff(v.y*0.70710678118654752f));
            v.z = 0.5f*v.z*(1.0f + erff(v.z*0.70710678118654752f));
            v.w = 0.5f*v.w*(1.0f + erff(v.w*0.70710678118654752f));
        }
        size_t co = ((size_t)b*Cstride + rowoff + t)*(size_t)N + n0 + tx*4;
        if (resid) {
            float4 r = *reinterpret_cast<const float4*>(&resid[co]);
            v.x+=r.x; v.y+=r.y; v.z+=r.z; v.w+=r.w;
        }
        if (posadd) {
            float4 p = *reinterpret_cast<const float4*>(&posadd[(size_t)(rowoff+t)*N + n0 + tx*4]);
            v.x+=p.x; v.y+=p.y; v.z+=p.z; v.w+=p.w;
        }
        *reinterpret_cast<float4*>(&C[co]) = v;
    }
}

// ---------------- K transpose + V norms fused ----------------
__global__ void __launch_bounds__(256) transp_k() {
    int T = g_T;
    int t0 = blockIdx.x * 32;
    if (t0 >= T) return;
    int bh = blockIdx.y;
    int b = bh / Hh, h = bh % Hh;
    int tid = threadIdx.x;
    __shared__ float tile[64][33];

    const float* base = g_qkv + (size_t)b*TMAX*QKVW + Dd + h*HD;
#pragma unroll
    for (int i = 0; i < 8; i++) {
        int idx = i*256 + tid;
        int r = idx >> 6, c = idx & 63;
        int t = t0 + r;
        float v = (t < T) ? base[(size_t)t*QKVW + c] : 0.f;
        tile[c][r] = v;
    }
    __syncthreads();
    float* kout = g_ktr + (size_t)bh*HD*KTS;
#pragma unroll
    for (int i = 0; i < 8; i++) {
        int idx = i*256 + tid;
        int dd = idx >> 5, tt = idx & 31;
        kout[(size_t)dd*KTS + t0 + tt] = tile[dd][tt];
    }

    // fused V norms: 8 warps x 4 tokens each
    int w = tid >> 5, lane = tid & 31;
    const float* vbase = g_qkv + (size_t)b*TMAX*QKVW + 2*Dd + h*HD;
#pragma unroll
    for (int j = 0; j < 4; j++) {
        int t = t0 + w*4 + j;
        if (t < T) {
            const float* v = vbase + (size_t)t*QKVW;
            float s = v[lane]*v[lane] + v[lane+32]*v[lane+32];
#pragma unroll
            for (int o=16;o;o>>=1) s += __shfl_xor_sync(0xffffffffu, s, o);
            if (!lane) g_vnorm[bh*TMAX + t] = sqrtf(s);
        }
    }
}

// ---------------- layernorm: warp per row ----------------
__global__ void ln_k(const float* __restrict__ in, float* __restrict__ out,
                     const float* __restrict__ sc, const float* __restrict__ bi,
                     int inStride, int outStride, int fixedT)
{
    int T = fixedT ? fixedT : g_T;
    int lane = threadIdx.x & 31, w = threadIdx.x >> 5;
    int t = blockIdx.x*4 + w;
    if (t >= T) return;
    int b = blockIdx.y;
    const float4* row = reinterpret_cast<const float4*>(in + ((size_t)b*inStride + t)*Dd);
    float4 v0=row[lane], v1=row[lane+32], v2=row[lane+64];
    float s = v0.x+v0.y+v0.z+v0.w + v1.x+v1.y+v1.z+v1.w + v2.x+v2.y+v2.z+v2.w;
#pragma unroll
    for (int o=16;o;o>>=1) s += __shfl_xor_sync(0xffffffffu, s, o);
    float mean = s*(1.0f/Dd);
    float4 d0,d1,d2;
    d0.x=v0.x-mean; d0.y=v0.y-mean; d0.z=v0.z-mean; d0.w=v0.w-mean;
    d1.x=v1.x-mean; d1.y=v1.y-mean; d1.z=v1.z-mean; d1.w=v1.w-mean;
    d2.x=v2.x-mean; d2.y=v2.y-mean; d2.z=v2.z-mean; d2.w=v2.w-mean;
    float q = d0.x*d0.x+d0.y*d0.y+d0.z*d0.z+d0.w*d0.w
            + d1.x*d1.x+d1.y*d1.y+d1.z*d1.z+d1.w*d1.w
            + d2.x*d2.x+d2.y*d2.y+d2.z*d2.z+d2.w*d2.w;
#pragma unroll
    for (int o=16;o;o>>=1) q += __shfl_xor_sync(0xffffffffu, q, o);
    float inv = 1.0f/sqrtf(q*(1.0f/Dd) + LN_EPSc);
    const float4* sc4 = reinterpret_cast<const float4*>(sc);
    const float4* bi4 = reinterpret_cast<const float4*>(bi);
    float4* orow = reinterpret_cast<float4*>(out + ((size_t)b*outStride + t)*Dd);
    float4 s0=sc4[lane], s1=sc4[lane+32], s2=sc4[lane+64];
    float4 b0=bi4[lane], b1=bi4[lane+32], b2=bi4[lane+64];
    float4 o0,o1,o2;
    o0.x=d0.x*inv*s0.x+b0.x; o0.y=d0.y*inv*s0.y+b0.y; o0.z=d0.z*inv*s0.z+b0.z; o0.w=d0.w*inv*s0.w+b0.w;
    o1.x=d1.x*inv*s1.x+b1.x; o1.y=d1.y*inv*s1.y+b1.y; o1.z=d1.z*inv*s1.z+b1.z; o1.w=d1.w*inv*s1.w+b1.w;
    o2.x=d2.x*inv*s2.x+b2.x; o2.y=d2.y*inv*s2.y+b2.y; o2.z=d2.z*inv*s2.z+b2.z; o2.w=d2.w*inv*s2.w+b2.w;
    orow[lane]=o0; orow[lane+32]=o1; orow[lane+64]=o2;
}

// ---------------- attention: 8 queries per block, 256 threads (R9 proven) ----
__global__ void __launch_bounds__(256) attn_k() {
    int T = g_T;
    int q0 = blockIdx.x * 8;
    if (q0 >= T) return;
    int bh = blockIdx.y;
    int b = bh / Hh, h = bh % Hh;
    int tid = threadIdx.x;

    __shared__ float sqT[HD][8];
    __shared__ float sc[8][TMAX];
    __shared__ float redsm[16][64];

    const float* base = g_qkv + (size_t)b*TMAX*QKVW;

    // load 8 q rows transposed: sqT[d][q]
    for (int e = tid; e < 8*HD; e += 256) {
        int q = e >> 6, d = e & 63;
        float v = 0.f;
        if (q0+q < T) v = base[(size_t)(q0+q)*QKVW + h*HD + d];
        sqT[d][q] = v;
    }
    __syncthreads();

    // scores: thread per key, coalesced K^T reads
    const float* kt = g_ktr + (size_t)bh*HD*KTS;
    for (int k = tid; k < T; k += 256) {
        float acc[8] = {0.f,0.f,0.f,0.f,0.f,0.f,0.f,0.f};
        const float* kp = kt + k;
#pragma unroll 8
        for (int d = 0; d < HD; d++) {
            float kv = kp[(size_t)d*KTS];
            float4 qa = *reinterpret_cast<const float4*>(&sqT[d][0]);
            float4 qb = *reinterpret_cast<const float4*>(&sqT[d][4]);
            acc[0] += kv*qa.x; acc[1] += kv*qa.y; acc[2] += kv*qa.z; acc[3] += kv*qa.w;
            acc[4] += kv*qb.x; acc[5] += kv*qb.y; acc[6] += kv*qb.z; acc[7] += kv*qb.w;
        }
#pragma unroll
        for (int q = 0; q < 8; q++) sc[q][k] = acc[q]*0.125f;
    }
    __syncthreads();

    // softmax: warp w handles query q0+w
    {
        int w = tid >> 5, lane = tid & 31;
        float m = -3.4e38f;
        for (int k=lane; k<T; k+=32) m = fmaxf(m, sc[w][k]);
#pragma unroll
        for (int o=16;o;o>>=1) m = fmaxf(m, __shfl_xor_sync(0xffffffffu, m, o));
        float s = 0.f;
        for (int k=lane; k<T; k+=32) { float e = expf(sc[w][k]-m); sc[w][k]=e; s+=e; }
#pragma unroll
        for (int o=16;o;o>>=1) s += __shfl_xor_sync(0xffffffffu, s, o);
        float inv = 1.0f/s;
        bool is_cls = (q0 + w == 0);
        for (int k=lane; k<T; k+=32) {
            float p = sc[w][k]*inv; sc[w][k]=p;
            if (is_cls) g_attn_cls[bh*TMAX + k] = p;
        }
    }
    __syncthreads();

    // AV: 16 segments x 16 d-groups
    int seg = tid >> 4, d4 = tid & 15;
    float4 a[8];
#pragma unroll
    for (int q=0;q<8;q++) a[q] = make_float4(0.f,0.f,0.f,0.f);
    for (int k = seg; k < T; k += 16) {
        float4 vv = *reinterpret_cast<const float4*>(base + (size_t)k*QKVW + 2*Dd + h*HD + d4*4);
#pragma unroll
        for (int q=0;q<8;q++) {
            float p = sc[q][k];
            a[q].x += p*vv.x; a[q].y += p*vv.y; a[q].z += p*vv.z; a[q].w += p*vv.w;
        }
    }
#pragma unroll
    for (int q=0;q<8;q++) {
        *reinterpret_cast<float4*>(&redsm[seg][d4*4]) = a[q];
        __syncthreads();
        if (tid < 64 && q0+q < T) {
            float s = 0.f;
#pragma unroll
            for (int sgi=0;sgi<16;sgi++) s += redsm[sgi][tid];
            g_ao[((size_t)b*TMAX + q0+q)*Dd + h*HD + tid] = s;
        }
        __syncthreads();
    }
}

// ---------------- per-batch stats ----------------
__global__ void stats_k() {
    int b = blockIdx.x, tid = threadIdx.x, T = g_T;
    __shared__ float red[256];
    for (int h = 0; h < Hh; h++) {
        float s = 0.f;
        for (int t = tid; t < T; t += 256) {
            float c = g_attn_cls[(b*Hh+h)*TMAX + t];
            s += c*logf(c + EPSc);
        }
        red[tid]=s; __syncthreads();
        for (int o=128;o;o>>=1){ if(tid<o) red[tid]+=red[tid+o]; __syncthreads(); }
        if (!tid) g_ent[b*Hh+h] = -red[0];
        __syncthreads();
    }
    int N = T-1;
    float loc = 0.f;
    for (int t=tid; t<N; t+=256) {
        float r = 0.f;
#pragma unroll
        for (int h=0;h<Hh;h++) {
            int o = (b*Hh+h)*TMAX + t+1;
            r += g_attn_cls[o]*g_vnorm[o];
        }
        g_raw[b*TMAX+t] = r; loc += r;
    }
    red[tid]=loc; __syncthreads();
    for (int o=128;o;o>>=1){ if(tid<o) red[tid]+=red[tid+o]; __syncthreads(); }
    if (!tid) g_mass[b] = red[0];
}

// ---------------- scores + decision + top-k selection ----------------
__global__ void keepsel_k() {
    int tid = threadIdx.x;
    int T = g_T, N = T-1;
    __shared__ float ssc[NMAX];
    __shared__ int sh_prune, sh_Nn;
    if (tid < N) {
        float s = 0.f;
#pragma unroll
        for (int b=0;b<Bz;b++) s += g_raw[b*TMAX+tid]/(g_mass[b]+EPSc);
        float sm = s*(1.0f/Bz);
        ssc[tid] = sm;
        g_scores[tid] = sm;
    }
    if (tid == 0) {
        int Nn = N, prune = 0;
        if (N > MIN_TOK) {
            float logT = logf((float)T);
            float rho_sum = 0.f;
            for (int b=0;b<Bz;b++) {
                float rb = 0.f;
                for (int h=0;h<Hh;h++) rb += g_ent[b*Hh+h]/logT;
                rho_sum += rb/(float)Hh;
            }
            float rho_mean = rho_sum/(float)Bz;
            if (g_prev_valid) {
                float ds = 0.f;
                for (int b=0;b<Bz;b++) ds += fabsf(g_mass[b]-g_prevmass[b])/(g_prevmass[b]+EPSc);
                float dm = ds/(float)Bz;
                float kr = 1.0f - GAMMAc*(rho_mean + dm);
                kr = fminf(fmaxf(kr, 0.0f), 1.0f);
                int cand = (int)((double)N*(double)kr);
                Nn = cand > MIN_TOK ? cand : MIN_TOK;
                if (Nn > N) Nn = N;
            }
            prune = (Nn < N) ? 1 : 0;
            for (int b=0;b<Bz;b++) g_prevmass[b] = g_mass[b];
            g_prev_valid = 1;
        }
        sh_prune = prune; sh_Nn = Nn;
        g_Tnew = Nn + 1;
    }
    __syncthreads();
    if (!sh_prune) {
        if (tid < T) g_keep[tid] = tid;
        return;
    }
    int Nn = sh_Nn;
    __shared__ unsigned char kept[NMAX];
    int isk = 0;
    if (tid < N) {
        float my = ssc[tid];
        int rank = 0;
        for (int j=0;j<N;j++) {
            float s = ssc[j];
            rank += (s > my) || (s == my && j < tid);
        }
        isk = (rank < Nn);
    }
    if (tid < NMAX) kept[tid] = (tid < N) ? (unsigned char)isk : 0;
    __syncthreads();
    if (tid < N && isk) {
        int pos = 1;
        for (int j=0;j<tid;j++) pos += kept[j];
        g_keep[pos] = tid + 1;
    }
    if (tid == 0) g_keep[0] = 0;
}

// ---------------- gather ----------------
__global__ void gather_k(const float* __restrict__ src, float* __restrict__ dst) {
    int pos = blockIdx.x;
    if (pos >= g_Tnew) return;
    int b = blockIdx.y;
    int s = g_keep[pos];
    const float4* sp = reinterpret_cast<const float4*>(src + ((size_t)b*TMAX + s)*Dd);
    float4* dp = reinterpret_cast<float4*>(dst + ((size_t)b*TMAX + pos)*Dd);
    if (threadIdx.x < 96) dp[threadIdx.x] = sp[threadIdx.x];
    if (pos==0 && b==0 && threadIdx.x==0) g_T = g_Tnew;
}

// ---------------- classifier head ----------------
__global__ void head_k(const float* __restrict__ hw, const float* __restrict__ hb,
                       float* __restrict__ out) {
    int b = blockIdx.y;
    __shared__ float xf[Dd];
    int tid = threadIdx.x;
    for (int d=tid; d<Dd; d+=256) xf[d] = g_cls[b*Dd+d];
    __syncthreads();
    int n = blockIdx.x*256 + tid;
    if (n < NCLSc) {
        float acc = hb[n];
        for (int k=0;k<Dd;k++) acc += xf[k]*hw[(size_t)k*NCLSc + n];
        out[(size_t)b*NCLSc + n] = acc;
    }
}

// ---------------- launch sequence ----------------
extern "C" void kernel_launch(void* const* d_in, const int* in_sizes, int n_in,
                              void* d_out, int out_size) {
    (void)in_sizes; (void)n_in; (void)out_size;
    const float* x        = (const float*)d_in[0];
    const float* patch_w  = (const float*)d_in[1];
    const float* patch_b  = (const float*)d_in[2];
    const float* cls_tok  = (const float*)d_in[3];
    const float* pos      = (const float*)d_in[4];
    const float* ln1_s    = (const float*)d_in[5];
    const float* ln1_b    = (const float*)d_in[6];
    const float* qkv_w    = (const float*)d_in[7];
    const float* qkv_b    = (const float*)d_in[8];
    const float* proj_w   = (const float*)d_in[9];
    const float* proj_b   = (const float*)d_in[10];
    const float* ln2_s    = (const float*)d_in[11];
    const float* ln2_b    = (const float*)d_in[12];
    const float* fc1_w    = (const float*)d_in[13];
    const float* fc1_b    = (const float*)d_in[14];
    const float* fc2_w    = (const float*)d_in[15];
    const float* fc2_b    = (const float*)d_in[16];
    const float* norm_s   = (const float*)d_in[17];
    const float* norm_b   = (const float*)d_in[18];
    const float* head_w   = (const float*)d_in[19];
    const float* head_b   = (const float*)d_in[20];
    float* out = (float*)d_out;

    float *pX,*pX2,*pXn,*pAo,*pQkv,*pH1,*pPat,*pCls;
    cudaGetSymbolAddress((void**)&pX,   g_x);
    cudaGetSymbolAddress((void**)&pX2,  g_x2);
    cudaGetSymbolAddress((void**)&pXn,  g_xn);
    cudaGetSymbolAddress((void**)&pAo,  g_ao);
    cudaGetSymbolAddress((void**)&pQkv, g_qkv);
    cudaGetSymbolAddress((void**)&pH1,  g_h1);
    cudaGetSymbolAddress((void**)&pPat, g_patches);
    cudaGetSymbolAddress((void**)&pCls, g_cls);

    init_k<<<Bz, Dd>>>(cls_tok, pos);
    {
        int tot = Bz*NMAX*Cc*Pp*Pp;
        patchify_k<<<(tot+255)/256, 256>>>(x);
    }
    gemm_k<<<dim3(9,6,Bz), 128>>>(pPat, patch_w, patch_b, pX, nullptr, pos,
                                  Cc*Pp*Pp, Dd, NMAX, TMAX, 1, NMAX, 0);

    float* bufs[2] = {pX, pX2};
    for (int l=0; l<Ll; l++) {
        float* cur = bufs[l & 1];
        float* nxt = bufs[(l+1) & 1];
        ln_k<<<dim3((TMAX+3)/4,Bz),128>>>(cur, pXn, ln1_s+l*Dd, ln1_b+l*Dd, TMAX, TMAX, 0);
        gemm_k<<<dim3(10,18,Bz), 128>>>(pXn, qkv_w + (size_t)l*Dd*QKVW, qkv_b + (size_t)l*QKVW,
                                        pQkv, nullptr, nullptr, Dd, QKVW, TMAX, TMAX, 0, 0, 0);
        transp_k<<<dim3((TMAX+31)/32, Bz*Hh), 256>>>();
        attn_k<<<dim3((TMAX+7)/8, Bz*Hh), 256>>>();
        gemm_k<<<dim3(10,6,Bz), 128>>>(pAo, proj_w + (size_t)l*Dd*Dd, proj_b + (size_t)l*Dd,
                                       cur, cur, nullptr, Dd, Dd, TMAX, TMAX, 0, 0, 0);
        ln_k<<<dim3((TMAX+3)/4,Bz),128>>>(cur, pXn, ln2_s+l*Dd, ln2_b+l*Dd, TMAX, TMAX, 0);
        gemm_k<<<dim3(10,24,Bz), 128>>>(pXn, fc1_w + (size_t)l*Dd*MLPd, fc1_b + (size_t)l*MLPd,
                                        pH1, nullptr, nullptr, Dd, MLPd, TMAX, TMAX, 0, 0, 1);
        gemm_k<<<dim3(10,6,Bz), 128>>>(pH1, fc2_w + (size_t)l*MLPd*Dd, fc2_b + (size_t)l*Dd,
                                       cur, cur, nullptr, MLPd, Dd, TMAX, TMAX, 0, 0, 0);
        stats_k<<<Bz, 256>>>();
        keepsel_k<<<1, 608>>>();
        gather_k<<<dim3(TMAX,Bz),128>>>(cur, nxt);
    }

    ln_k<<<dim3(1,Bz),128>>>(bufs[0], pCls, norm_s, norm_b, TMAX, 1, 1);
    head_k<<<dim3(4,Bz),256>>>(head_w, head_b, out);
}

// round 12
// speedup vs baseline: 1.0368x; 1.0050x over previous
#include <cuda_runtime.h>
#include <math.h>
#include <stdint.h>

#define Bz 8
#define Cc 3
#define IMGc 384
#define Pp 16
#define Gg 24
#define Dd 384
#define Hh 6
#define HD 64
#define Ll 12
#define MLPd 1536
#define NCLSc 1000
#define TMAX 577
#define NMAX 576
#define KTS 608
#define EPSc 1e-6f
#define LN_EPSc 1e-5f
#define GAMMAc 0.1f
#define MIN_TOK 16
#define QKVW (3*Dd)

// ---------------- device scratch ----------------
__device__ float g_x[Bz*TMAX*Dd];
__device__ float g_x2[Bz*TMAX*Dd];
__device__ float g_xn[Bz*TMAX*Dd];
__device__ float g_ao[Bz*TMAX*Dd];
__device__ float g_qkv[Bz*TMAX*QKVW];
__device__ float g_ktr[Bz*Hh*HD*KTS];
__device__ float g_h1[Bz*TMAX*MLPd];
__device__ float g_patches[Bz*NMAX*Cc*Pp*Pp];
__device__ float g_attn_cls[Bz*Hh*TMAX];
__device__ float g_vnorm[Bz*Hh*TMAX];
__device__ float g_ent[Bz*Hh];
__device__ float g_raw[Bz*TMAX];
__device__ float g_mass[Bz];
__device__ float g_prevmass[Bz];
__device__ float g_scores[NMAX];
__device__ int   g_keep[TMAX];
__device__ float g_cls[Bz*Dd];
__device__ int g_T, g_Tnew, g_prev_valid;

// ---------------- init ----------------
__global__ void init_k(const float* __restrict__ cls_token, const float* __restrict__ pos) {
    int b = blockIdx.x, d = threadIdx.x;
    g_x[((size_t)b*TMAX)*Dd + d] = cls_token[d] + pos[d];
    if (b == 0 && d == 0) { g_T = TMAX; g_prev_valid = 0; }
}

// ---------------- patch extraction ----------------
__global__ void patchify_k(const float* __restrict__ x) {
    int idx = blockIdx.x*blockDim.x + threadIdx.x;
    if (idx >= Bz*NMAX*(Cc*Pp*Pp)) return;
    int k = idx % (Cc*Pp*Pp);
    int g = (idx/(Cc*Pp*Pp)) % NMAX;
    int b = idx/((Cc*Pp*Pp)*NMAX);
    int px = k & 15, py = (k>>4)&15, c = k>>8;
    int gx = g % Gg, gy = g / Gg;
    g_patches[idx] = x[(((size_t)b*Cc + c)*IMGc + gy*Pp+py)*IMGc + gx*Pp+px];
}

// ---------------- tiled fp32 GEMM: 64x64 tile, 128 threads, 8x4 microtile ----
__global__ void __launch_bounds__(128) gemm_k(
    const float* __restrict__ A, const float* __restrict__ W,
    const float* __restrict__ bias, float* __restrict__ C,
    const float* __restrict__ resid, const float* __restrict__ posadd,
    int K, int N, int Astride, int Cstride, int rowoff, int fixedT, int act)
{
    int T = fixedT ? fixedT : g_T;
    int t0 = blockIdx.x * 64;
    if (t0 >= T) return;
    int n0 = blockIdx.y * 64;
    int b  = blockIdx.z;
    const float* Ab = A + (size_t)b * Astride * K;

    __shared__ float As[16][64];
    __shared__ float Ws[16][64];

    int tid = threadIdx.x;
    int tx = tid & 15, ty = tid >> 4;
    int arow = tid >> 2, aq = tid & 3;
    int wrow = tid >> 4, wq = tid & 15;

    float acc[8][4];
#pragma unroll
    for (int i=0;i<8;i++)
#pragma unroll
        for (int j=0;j<4;j++) acc[i][j]=0.f;

    for (int k0 = 0; k0 < K; k0 += 16) {
        {
            int t = t0 + arow;
            float4 v = make_float4(0.f,0.f,0.f,0.f);
            if (t < T) v = *reinterpret_cast<const float4*>(Ab + (size_t)t*K + k0 + aq*4);
            As[aq*4+0][arow]=v.x; As[aq*4+1][arow]=v.y; As[aq*4+2][arow]=v.z; As[aq*4+3][arow]=v.w;
            t = t0 + arow + 32;
            v = make_float4(0.f,0.f,0.f,0.f);
            if (t < T) v = *reinterpret_cast<const float4*>(Ab + (size_t)t*K + k0 + aq*4);
            As[aq*4+0][arow+32]=v.x; As[aq*4+1][arow+32]=v.y; As[aq*4+2][arow+32]=v.z; As[aq*4+3][arow+32]=v.w;
        }
        *reinterpret_cast<float4*>(&Ws[wrow][wq*4])   = *reinterpret_cast<const float4*>(W + (size_t)(k0+wrow)*N   + n0 + wq*4);
        *reinterpret_cast<float4*>(&Ws[wrow+8][wq*4]) = *reinterpret_cast<const float4*>(W + (size_t)(k0+wrow+8)*N + n0 + wq*4);
        __syncthreads();
#pragma unroll
        for (int kk = 0; kk < 16; kk++) {
            float4 wv = *reinterpret_cast<const float4*>(&Ws[kk][tx*4]);
            float4 a0 = *reinterpret_cast<const float4*>(&As[kk][ty*8]);
            float4 a1 = *reinterpret_cast<const float4*>(&As[kk][ty*8+4]);
            acc[0][0]+=a0.x*wv.x; acc[0][1]+=a0.x*wv.y; acc[0][2]+=a0.x*wv.z; acc[0][3]+=a0.x*wv.w;
            acc[1][0]+=a0.y*wv.x; acc[1][1]+=a0.y*wv.y; acc[1][2]+=a0.y*wv.z; acc[1][3]+=a0.y*wv.w;
            acc[2][0]+=a0.z*wv.x; acc[2][1]+=a0.z*wv.y; acc[2][2]+=a0.z*wv.z; acc[2][3]+=a0.z*wv.w;
            acc[3][0]+=a0.w*wv.x; acc[3][1]+=a0.w*wv.y; acc[3][2]+=a0.w*wv.z; acc[3][3]+=a0.w*wv.w;
            acc[4][0]+=a1.x*wv.x; acc[4][1]+=a1.x*wv.y; acc[4][2]+=a1.x*wv.z; acc[4][3]+=a1.x*wv.w;
            acc[5][0]+=a1.y*wv.x; acc[5][1]+=a1.y*wv.y; acc[5][2]+=a1.y*wv.z; acc[5][3]+=a1.y*wv.w;
            acc[6][0]+=a1.z*wv.x; acc[6][1]+=a1.z*wv.y; acc[6][2]+=a1.z*wv.z; acc[6][3]+=a1.z*wv.w;
            acc[7][0]+=a1.w*wv.x; acc[7][1]+=a1.w*wv.y; acc[7][2]+=a1.w*wv.z; acc[7][3]+=a1.w*wv.w;
        }
        __syncthreads();
    }

    float4 bv = *reinterpret_cast<const float4*>(&bias[n0 + tx*4]);
#pragma unroll
    for (int i = 0; i < 8; i++) {
        int t = t0 + ty*8 + i;
        if (t >= T) continue;
        float4 v;
        v.x = acc[i][0]+bv.x; v.y = acc[i][1]+bv.y; v.z = acc[i][2]+bv.z; v.w = acc[i][3]+bv.w;
        if (act) {
            v.x = 0.5f*v.x*(1.0f + erff(v.x*0.70710678118654752f));
            v.y = 0.5f*v.y*(1.0f + erff(v.y*0.70710678118654752f));
            v.z = 0.5f*v.z*(1.0f + erff(v.z*0.70710678118654752f));
            v.w = 0.5f*v.w*(1.0f + erff(v.w*0.70710678118654752f));
        }
        size_t co = ((size_t)b*Cstride + rowoff + t)*(size_t)N + n0 + tx*4;
        if (resid) {
            float4 r = *reinterpret_cast<const float4*>(&resid[co]);
            v.x+=r.x; v.y+=r.y; v.z+=r.z; v.w+=r.w;
        }
        if (posadd) {
            float4 p = *reinterpret_cast<const float4*>(&posadd[(size_t)(rowoff+t)*N + n0 + tx*4]);
            v.x+=p.x; v.y+=p.y; v.z+=p.z; v.w+=p.w;
        }
        *reinterpret_cast<float4*>(&C[co]) = v;
    }
}

// ---------------- K transpose + V norms fused ----------------
__global__ void __launch_bounds__(256) transp_k() {
    int T = g_T;
    int t0 = blockIdx.x * 32;
    if (t0 >= T) return;
    int bh = blockIdx.y;
    int b = bh / Hh, h = bh % Hh;
    int tid = threadIdx.x;
    __shared__ float tile[64][33];

    const float* base = g_qkv + (size_t)b*TMAX*QKVW + Dd + h*HD;
#pragma unroll
    for (int i = 0; i < 8; i++) {
        int idx = i*256 + tid;
        int r = idx >> 6, c = idx & 63;
        int t = t0 + r;
        float v = (t < T) ? base[(size_t)t*QKVW + c] : 0.f;
        tile[c][r] = v;
    }
    __syncthreads();
    float* kout = g_ktr + (size_t)bh*HD*KTS;
#pragma unroll
    for (int i = 0; i < 8; i++) {
        int idx = i*256 + tid;
        int dd = idx >> 5, tt = idx & 31;
        kout[(size_t)dd*KTS + t0 + tt] = tile[dd][tt];
    }

    // fused V norms: 8 warps x 4 tokens each
    int w = tid >> 5, lane = tid & 31;
    const float* vbase = g_qkv + (size_t)b*TMAX*QKVW + 2*Dd + h*HD;
#pragma unroll
    for (int j = 0; j < 4; j++) {
        int t = t0 + w*4 + j;
        if (t < T) {
            const float* v = vbase + (size_t)t*QKVW;
            float s = v[lane]*v[lane] + v[lane+32]*v[lane+32];
#pragma unroll
            for (int o=16;o;o>>=1) s += __shfl_xor_sync(0xffffffffu, s, o);
            if (!lane) g_vnorm[bh*TMAX + t] = sqrtf(s);
        }
    }
}

// ---------------- layernorm: warp per row ----------------
__global__ void ln_k(const float* __restrict__ in, float* __restrict__ out,
                     const float* __restrict__ sc, const float* __restrict__ bi,
                     int inStride, int outStride, int fixedT)
{
    int T = fixedT ? fixedT : g_T;
    int lane = threadIdx.x & 31, w = threadIdx.x >> 5;
    int t = blockIdx.x*4 + w;
    if (t >= T) return;
    int b = blockIdx.y;
    const float4* row = reinterpret_cast<const float4*>(in + ((size_t)b*inStride + t)*Dd);
    float4 v0=row[lane], v1=row[lane+32], v2=row[lane+64];
    float s = v0.x+v0.y+v0.z+v0.w + v1.x+v1.y+v1.z+v1.w + v2.x+v2.y+v2.z+v2.w;
#pragma unroll
    for (int o=16;o;o>>=1) s += __shfl_xor_sync(0xffffffffu, s, o);
    float mean = s*(1.0f/Dd);
    float4 d0,d1,d2;
    d0.x=v0.x-mean; d0.y=v0.y-mean; d0.z=v0.z-mean; d0.w=v0.w-mean;
    d1.x=v1.x-mean; d1.y=v1.y-mean; d1.z=v1.z-mean; d1.w=v1.w-mean;
    d2.x=v2.x-mean; d2.y=v2.y-mean; d2.z=v2.z-mean; d2.w=v2.w-mean;
    float q = d0.x*d0.x+d0.y*d0.y+d0.z*d0.z+d0.w*d0.w
            + d1.x*d1.x+d1.y*d1.y+d1.z*d1.z+d1.w*d1.w
            + d2.x*d2.x+d2.y*d2.y+d2.z*d2.z+d2.w*d2.w;
#pragma unroll
    for (int o=16;o;o>>=1) q += __shfl_xor_sync(0xffffffffu, q, o);
    float inv = 1.0f/sqrtf(q*(1.0f/Dd) + LN_EPSc);
    const float4* sc4 = reinterpret_cast<const float4*>(sc);
    const float4* bi4 = reinterpret_cast<const float4*>(bi);
    float4* orow = reinterpret_cast<float4*>(out + ((size_t)b*outStride + t)*Dd);
    float4 s0=sc4[lane], s1=sc4[lane+32], s2=sc4[lane+64];
    float4 b0=bi4[lane], b1=bi4[lane+32], b2=bi4[lane+64];
    float4 o0,o1,o2;
    o0.x=d0.x*inv*s0.x+b0.x; o0.y=d0.y*inv*s0.y+b0.y; o0.z=d0.z*inv*s0.z+b0.z; o0.w=d0.w*inv*s0.w+b0.w;
    o1.x=d1.x*inv*s1.x+b1.x; o1.y=d1.y*inv*s1.y+b1.y; o1.z=d1.z*inv*s1.z+b1.z; o1.w=d1.w*inv*s1.w+b1.w;
    o2.x=d2.x*inv*s2.x+b2.x; o2.y=d2.y*inv*s2.y+b2.y; o2.z=d2.z*inv*s2.z+b2.z; o2.w=d2.w*inv*s2.w+b2.w;
    orow[lane]=o0; orow[lane+32]=o1; orow[lane+64]=o2;
}

// ---------------- attention: 8 queries per block, 256 threads (R9 proven) ----
__global__ void __launch_bounds__(256) attn_k() {
    int T = g_T;
    int q0 = blockIdx.x * 8;
    if (q0 >= T) return;
    int bh = blockIdx.y;
    int b = bh / Hh, h = bh % Hh;
    int tid = threadIdx.x;

    __shared__ float sqT[HD][8];
    __shared__ float sc[8][TMAX];
    __shared__ float redsm[16][64];

    const float* base = g_qkv + (size_t)b*TMAX*QKVW;

    // load 8 q rows transposed: sqT[d][q]
    for (int e = tid; e < 8*HD; e += 256) {
        int q = e >> 6, d = e & 63;
        float v = 0.f;
        if (q0+q < T) v = base[(size_t)(q0+q)*QKVW + h*HD + d];
        sqT[d][q] = v;
    }
    __syncthreads();

    // scores: thread per key, coalesced K^T reads
    const float* kt = g_ktr + (size_t)bh*HD*KTS;
    for (int k = tid; k < T; k += 256) {
        float acc[8] = {0.f,0.f,0.f,0.f,0.f,0.f,0.f,0.f};
        const float* kp = kt + k;
#pragma unroll 8
        for (int d = 0; d < HD; d++) {
            float kv = kp[(size_t)d*KTS];
            float4 qa = *reinterpret_cast<const float4*>(&sqT[d][0]);
            float4 qb = *reinterpret_cast<const float4*>(&sqT[d][4]);
            acc[0] += kv*qa.x; acc[1] += kv*qa.y; acc[2] += kv*qa.z; acc[3] += kv*qa.w;
            acc[4] += kv*qb.x; acc[5] += kv*qb.y; acc[6] += kv*qb.z; acc[7] += kv*qb.w;
        }
#pragma unroll
        for (int q = 0; q < 8; q++) sc[q][k] = acc[q]*0.125f;
    }
    __syncthreads();

    // softmax: warp w handles query q0+w
    {
        int w = tid >> 5, lane = tid & 31;
        float m = -3.4e38f;
        for (int k=lane; k<T; k+=32) m = fmaxf(m, sc[w][k]);
#pragma unroll
        for (int o=16;o;o>>=1) m = fmaxf(m, __shfl_xor_sync(0xffffffffu, m, o));
        float s = 0.f;
        for (int k=lane; k<T; k+=32) { float e = expf(sc[w][k]-m); sc[w][k]=e; s+=e; }
#pragma unroll
        for (int o=16;o;o>>=1) s += __shfl_xor_sync(0xffffffffu, s, o);
        float inv = 1.0f/s;
        bool is_cls = (q0 + w == 0);
        for (int k=lane; k<T; k+=32) {
            float p = sc[w][k]*inv; sc[w][k]=p;
            if (is_cls) g_attn_cls[bh*TMAX + k] = p;
        }
    }
    __syncthreads();

    // AV: 16 segments x 16 d-groups
    int seg = tid >> 4, d4 = tid & 15;
    float4 a[8];
#pragma unroll
    for (int q=0;q<8;q++) a[q] = make_float4(0.f,0.f,0.f,0.f);
    for (int k = seg; k < T; k += 16) {
        float4 vv = *reinterpret_cast<const float4*>(base + (size_t)k*QKVW + 2*Dd + h*HD + d4*4);
#pragma unroll
        for (int q=0;q<8;q++) {
            float p = sc[q][k];
            a[q].x += p*vv.x; a[q].y += p*vv.y; a[q].z += p*vv.z; a[q].w += p*vv.w;
        }
    }
#pragma unroll
    for (int q=0;q<8;q++) {
        *reinterpret_cast<float4*>(&redsm[seg][d4*4]) = a[q];
        __syncthreads();
        if (tid < 64 && q0+q < T) {
            float s = 0.f;
#pragma unroll
            for (int sgi=0;sgi<16;sgi++) s += redsm[sgi][tid];
            g_ao[((size_t)b*TMAX + q0+q)*Dd + h*HD + tid] = s;
        }
        __syncthreads();
    }
}

// ---------------- per-batch stats ----------------
__global__ void stats_k() {
    int b = blockIdx.x, tid = threadIdx.x, T = g_T;
    __shared__ float red[256];
    for (int h = 0; h < Hh; h++) {
        float s = 0.f;
        for (int t = tid; t < T; t += 256) {
            float c = g_attn_cls[(b*Hh+h)*TMAX + t];
            s += c*logf(c + EPSc);
        }
        red[tid]=s; __syncthreads();
        for (int o=128;o;o>>=1){ if(tid<o) red[tid]+=red[tid+o]; __syncthreads(); }
        if (!tid) g_ent[b*Hh+h] = -red[0];
        __syncthreads();
    }
    int N = T-1;
    float loc = 0.f;
    for (int t=tid; t<N; t+=256) {
        float r = 0.f;
#pragma unroll
        for (int h=0;h<Hh;h++) {
            int o = (b*Hh+h)*TMAX + t+1;
            r += g_attn_cls[o]*g_vnorm[o];
        }
        g_raw[b*TMAX+t] = r; loc += r;
    }
    red[tid]=loc; __syncthreads();
    for (int o=128;o;o>>=1){ if(tid<o) red[tid]+=red[tid+o]; __syncthreads(); }
    if (!tid) g_mass[b] = red[0];
}

// ---------------- scores + decision + top-k selection ----------------
__global__ void keepsel_k() {
    int tid = threadIdx.x;
    int T = g_T, N = T-1;
    __shared__ float ssc[NMAX];
    __shared__ int sh_prune, sh_Nn;
    if (tid < N) {
        float s = 0.f;
#pragma unroll
        for (int b=0;b<Bz;b++) s += g_raw[b*TMAX+tid]/(g_mass[b]+EPSc);
        float sm = s*(1.0f/Bz);
        ssc[tid] = sm;
        g_scores[tid] = sm;
    }
    if (tid == 0) {
        int Nn = N, prune = 0;
        if (N > MIN_TOK) {
            float logT = logf((float)T);
            float rho_sum = 0.f;
            for (int b=0;b<Bz;b++) {
                float rb = 0.f;
                for (int h=0;h<Hh;h++) rb += g_ent[b*Hh+h]/logT;
                rho_sum += rb/(float)Hh;
            }
            float rho_mean = rho_sum/(float)Bz;
            if (g_prev_valid) {
                float ds = 0.f;
                for (int b=0;b<Bz;b++) ds += fabsf(g_mass[b]-g_prevmass[b])/(g_prevmass[b]+EPSc);
                float dm = ds/(float)Bz;
                float kr = 1.0f - GAMMAc*(rho_mean + dm);
                kr = fminf(fmaxf(kr, 0.0f), 1.0f);
                int cand = (int)((double)N*(double)kr);
                Nn = cand > MIN_TOK ? cand : MIN_TOK;
                if (Nn > N) Nn = N;
            }
            prune = (Nn < N) ? 1 : 0;
            for (int b=0;b<Bz;b++) g_prevmass[b] = g_mass[b];
            g_prev_valid = 1;
        }
        sh_prune = prune; sh_Nn = Nn;
        g_Tnew = Nn + 1;
    }
    __syncthreads();
    if (!sh_prune) {
        if (tid < T) g_keep[tid] = tid;
        return;
    }
    int Nn = sh_Nn;
    __shared__ unsigned char kept[NMAX];
    int isk = 0;
    if (tid < N) {
        float my = ssc[tid];
        int rank = 0;
        for (int j=0;j<N;j++) {
            float s = ssc[j];
            rank += (s > my) || (s == my && j < tid);
        }
        isk = (rank < Nn);
    }
    if (tid < NMAX) kept[tid] = (tid < N) ? (unsigned char)isk : 0;
    __syncthreads();
    if (tid < N && isk) {
        int pos = 1;
        for (int j=0;j<tid;j++) pos += kept[j];
        g_keep[pos] = tid + 1;
    }
    if (tid == 0) g_keep[0] = 0;
}

// ---------------- gather ----------------
__global__ void gather_k(const float* __restrict__ src, float* __restrict__ dst) {
    int pos = blockIdx.x;
    if (pos >= g_Tnew) return;
    int b = blockIdx.y;
    int s = g_keep[pos];
    const float4* sp = reinterpret_cast<const float4*>(src + ((size_t)b*TMAX + s)*Dd);
    float4* dp = reinterpret_cast<float4*>(dst + ((size_t)b*TMAX + pos)*Dd);
    if (threadIdx.x < 96) dp[threadIdx.x] = sp[threadIdx.x];
    if (pos==0 && b==0 && threadIdx.x==0) g_T = g_Tnew;
}

// ---------------- classifier head ----------------
__global__ void head_k(const float* __restrict__ hw, const float* __restrict__ hb,
                       float* __restrict__ out) {
    int b = blockIdx.y;
    __shared__ float xf[Dd];
    int tid = threadIdx.x;
    for (int d=tid; d<Dd; d+=256) xf[d] = g_cls[b*Dd+d];
    __syncthreads();
    int n = blockIdx.x*256 + tid;
    if (n < NCLSc) {
        float acc = hb[n];
        for (int k=0;k<Dd;k++) acc += xf[k]*hw[(size_t)k*NCLSc + n];
        out[(size_t)b*NCLSc + n] = acc;
    }
}

// ---------------- launch sequence ----------------
extern "C" void kernel_launch(void* const* d_in, const int* in_sizes, int n_in,
                              void* d_out, int out_size) {
    (void)in_sizes; (void)n_in; (void)out_size;
    const float* x        = (const float*)d_in[0];
    const float* patch_w  = (const float*)d_in[1];
    const float* patch_b  = (const float*)d_in[2];
    const float* cls_tok  = (const float*)d_in[3];
    const float* pos      = (const float*)d_in[4];
    const float* ln1_s    = (const float*)d_in[5];
    const float* ln1_b    = (const float*)d_in[6];
    const float* qkv_w    = (const float*)d_in[7];
    const float* qkv_b    = (const float*)d_in[8];
    const float* proj_w   = (const float*)d_in[9];
    const float* proj_b   = (const float*)d_in[10];
    const float* ln2_s    = (const float*)d_in[11];
    const float* ln2_b    = (const float*)d_in[12];
    const float* fc1_w    = (const float*)d_in[13];
    const float* fc1_b    = (const float*)d_in[14];
    const float* fc2_w    = (const float*)d_in[15];
    const float* fc2_b    = (const float*)d_in[16];
    const float* norm_s   = (const float*)d_in[17];
    const float* norm_b   = (const float*)d_in[18];
    const float* head_w   = (const float*)d_in[19];
    const float* head_b   = (const float*)d_in[20];
    float* out = (float*)d_out;

    float *pX,*pX2,*pXn,*pAo,*pQkv,*pH1,*pPat,*pCls;
    cudaGetSymbolAddress((void**)&pX,   g_x);
    cudaGetSymbolAddress((void**)&pX2,  g_x2);
    cudaGetSymbolAddress((void**)&pXn,  g_xn);
    cudaGetSymbolAddress((void**)&pAo,  g_ao);
    cudaGetSymbolAddress((void**)&pQkv, g_qkv);
    cudaGetSymbolAddress((void**)&pH1,  g_h1);
    cudaGetSymbolAddress((void**)&pPat, g_patches);
    cudaGetSymbolAddress((void**)&pCls, g_cls);

    init_k<<<Bz, Dd>>>(cls_tok, pos);
    {
        int tot = Bz*NMAX*Cc*Pp*Pp;
        patchify_k<<<(tot+255)/256, 256>>>(x);
    }
    gemm_k<<<dim3(9,6,Bz), 128>>>(pPat, patch_w, patch_b, pX, nullptr, pos,
                                  Cc*Pp*Pp, Dd, NMAX, TMAX, 1, NMAX, 0);

    float* bufs[2] = {pX, pX2};
    for (int l=0; l<Ll; l++) {
        float* cur = bufs[l & 1];
        float* nxt = bufs[(l+1) & 1];
        ln_k<<<dim3((TMAX+3)/4,Bz),128>>>(cur, pXn, ln1_s+l*Dd, ln1_b+l*Dd, TMAX, TMAX, 0);
        gemm_k<<<dim3(10,18,Bz), 128>>>(pXn, qkv_w + (size_t)l*Dd*QKVW, qkv_b + (size_t)l*QKVW,
                                        pQkv, nullptr, nullptr, Dd, QKVW, TMAX, TMAX, 0, 0, 0);
        transp_k<<<dim3((TMAX+31)/32, Bz*Hh), 256>>>();
        attn_k<<<dim3((TMAX+7)/8, Bz*Hh), 256>>>();
        gemm_k<<<dim3(10,6,Bz), 128>>>(pAo, proj_w + (size_t)l*Dd*Dd, proj_b + (size_t)l*Dd,
                                       cur, cur, nullptr, Dd, Dd, TMAX, TMAX, 0, 0, 0);
        ln_k<<<dim3((TMAX+3)/4,Bz),128>>>(cur, pXn, ln2_s+l*Dd, ln2_b+l*Dd, TMAX, TMAX, 0);
        gemm_k<<<dim3(10,24,Bz), 128>>>(pXn, fc1_w + (size_t)l*Dd*MLPd, fc1_b + (size_t)l*MLPd,
                                        pH1, nullptr, nullptr, Dd, MLPd, TMAX, TMAX, 0, 0, 1);
        gemm_k<<<dim3(10,6,Bz), 128>>>(pH1, fc2_w + (size_t)l*MLPd*Dd, fc2_b + (size_t)l*Dd,
                                       cur, cur, nullptr, MLPd, Dd, TMAX, TMAX, 0, 0, 0);
        stats_k<<<Bz, 256>>>();
        keepsel_k<<<1, 608>>>();
        gather_k<<<dim3(TMAX,Bz),128>>>(cur, nxt);
    }

    ln_k<<<dim3(1,Bz),128>>>(bufs[0], pCls, norm_s, norm_b, TMAX, 1, 1);
    head_k<<<dim3(4,Bz),256>>>(head_w, head_b, out);
}

// round 13
// speedup vs baseline: 1.0730x; 1.0349x over previous
#include <cuda_runtime.h>
#include <math.h>
#include <stdint.h>

#define Bz 8
#define Cc 3
#define IMGc 384
#define Pp 16
#define Gg 24
#define Dd 384
#define Hh 6
#define HD 64
#define Ll 12
#define MLPd 1536
#define NCLSc 1000
#define TMAX 577
#define NMAX 576
#define KTS 608
#define EPSc 1e-6f
#define LN_EPSc 1e-5f
#define GAMMAc 0.1f
#define MIN_TOK 16
#define QKVW (3*Dd)

// ---------------- device scratch ----------------
__device__ float g_x[Bz*TMAX*Dd];
__device__ float g_x2[Bz*TMAX*Dd];
__device__ float g_xn[Bz*TMAX*Dd];
__device__ float g_ao[Bz*TMAX*Dd];
__device__ float g_qkv[Bz*TMAX*QKVW];
__device__ float g_ktr[Bz*Hh*HD*KTS];
__device__ float g_h1[Bz*TMAX*MLPd];
__device__ float g_patches[Bz*NMAX*Cc*Pp*Pp];
__device__ float g_attn_cls[Bz*Hh*TMAX];
__device__ float g_vnorm[Bz*Hh*TMAX];
__device__ float g_ent[Bz*Hh];
__device__ float g_raw[Bz*TMAX];
__device__ float g_mass[Bz];
__device__ float g_prevmass[Bz];
__device__ float g_scores[NMAX];
__device__ int   g_keep[TMAX];
__device__ float g_cls[Bz*Dd];
__device__ int g_T, g_Tnew, g_prev_valid;

// ---------------- init ----------------
__global__ void init_k(const float* __restrict__ cls_token, const float* __restrict__ pos) {
    int b = blockIdx.x, d = threadIdx.x;
    g_x[((size_t)b*TMAX)*Dd + d] = cls_token[d] + pos[d];
    if (b == 0 && d == 0) { g_T = TMAX; g_prev_valid = 0; }
}

// ---------------- patch extraction ----------------
__global__ void patchify_k(const float* __restrict__ x) {
    int idx = blockIdx.x*blockDim.x + threadIdx.x;
    if (idx >= Bz*NMAX*(Cc*Pp*Pp)) return;
    int k = idx % (Cc*Pp*Pp);
    int g = (idx/(Cc*Pp*Pp)) % NMAX;
    int b = idx/((Cc*Pp*Pp)*NMAX);
    int px = k & 15, py = (k>>4)&15, c = k>>8;
    int gx = g % Gg, gy = g / Gg;
    g_patches[idx] = x[(((size_t)b*Cc + c)*IMGc + gy*Pp+py)*IMGc + gx*Pp+px];
}

// ---------------- tiled fp32 GEMM: 64x64 tile, 128 threads, 8x4 micro, k-tile 32
__global__ void __launch_bounds__(128) gemm_k(
    const float* __restrict__ A, const float* __restrict__ W,
    const float* __restrict__ bias, float* __restrict__ C,
    const float* __restrict__ resid, const float* __restrict__ posadd,
    int K, int N, int Astride, int Cstride, int rowoff, int fixedT, int act)
{
    int T = fixedT ? fixedT : g_T;
    int t0 = blockIdx.x * 64;
    if (t0 >= T) return;
    int n0 = blockIdx.y * 64;
    int b  = blockIdx.z;
    const float* Ab = A + (size_t)b * Astride * K;

    __shared__ float As[32][64];   // transposed: As[kk][row]
    __shared__ float Ws[32][64];

    int tid = threadIdx.x;
    int tx = tid & 15, ty = tid >> 4;
    int arow = tid >> 1, ak = (tid & 1) * 16;   // A: row 0..63, k-offset 0/16

    float acc[8][4];
#pragma unroll
    for (int i=0;i<8;i++)
#pragma unroll
        for (int j=0;j<4;j++) acc[i][j]=0.f;

    int art = t0 + arow;
    bool aok = (art < T);
    const float* arow_p = Ab + (size_t)art*K + ak;

    for (int k0 = 0; k0 < K; k0 += 32) {
        // --- fill A (transposed): 4 float4 per thread ---
#pragma unroll
        for (int j = 0; j < 4; j++) {
            float4 v = aok ? *reinterpret_cast<const float4*>(arow_p + k0 + j*4)
                           : make_float4(0.f,0.f,0.f,0.f);
            As[ak+j*4+0][arow]=v.x; As[ak+j*4+1][arow]=v.y;
            As[ak+j*4+2][arow]=v.z; As[ak+j*4+3][arow]=v.w;
        }
        // --- fill W: 4 float4 per thread, coalesced ---
#pragma unroll
        for (int j = 0; j < 4; j++) {
            int lin = tid + j*128;
            int kr = lin >> 4, c4 = lin & 15;
            *reinterpret_cast<float4*>(&Ws[kr][c4*4]) =
                *reinterpret_cast<const float4*>(W + (size_t)(k0+kr)*N + n0 + c4*4);
        }
        __syncthreads();
#pragma unroll
        for (int kk = 0; kk < 32; kk++) {
            float4 wv = *reinterpret_cast<const float4*>(&Ws[kk][tx*4]);
            float4 a0 = *reinterpret_cast<const float4*>(&As[kk][ty*8]);
            float4 a1 = *reinterpret_cast<const float4*>(&As[kk][ty*8+4]);
            acc[0][0]+=a0.x*wv.x; acc[0][1]+=a0.x*wv.y; acc[0][2]+=a0.x*wv.z; acc[0][3]+=a0.x*wv.w;
            acc[1][0]+=a0.y*wv.x; acc[1][1]+=a0.y*wv.y; acc[1][2]+=a0.y*wv.z; acc[1][3]+=a0.y*wv.w;
            acc[2][0]+=a0.z*wv.x; acc[2][1]+=a0.z*wv.y; acc[2][2]+=a0.z*wv.z; acc[2][3]+=a0.z*wv.w;
            acc[3][0]+=a0.w*wv.x; acc[3][1]+=a0.w*wv.y; acc[3][2]+=a0.w*wv.z; acc[3][3]+=a0.w*wv.w;
            acc[4][0]+=a1.x*wv.x; acc[4][1]+=a1.x*wv.y; acc[4][2]+=a1.x*wv.z; acc[4][3]+=a1.x*wv.w;
            acc[5][0]+=a1.y*wv.x; acc[5][1]+=a1.y*wv.y; acc[5][2]+=a1.y*wv.z; acc[5][3]+=a1.y*wv.w;
            acc[6][0]+=a1.z*wv.x; acc[6][1]+=a1.z*wv.y; acc[6][2]+=a1.z*wv.z; acc[6][3]+=a1.z*wv.w;
            acc[7][0]+=a1.w*wv.x; acc[7][1]+=a1.w*wv.y; acc[7][2]+=a1.w*wv.z; acc[7][3]+=a1.w*wv.w;
        }
        __syncthreads();
    }

    float4 bv = *reinterpret_cast<const float4*>(&bias[n0 + tx*4]);
#pragma unroll
    for (int i = 0; i < 8; i++) {
        int t = t0 + ty*8 + i;
        if (t >= T) continue;
        float4 v;
        v.x = acc[i][0]+bv.x; v.y = acc[i][1]+bv.y; v.z = acc[i][2]+bv.z; v.w = acc[i][3]+bv.w;
        if (act) {
            v.x = 0.5f*v.x*(1.0f + erff(v.x*0.70710678118654752f));
            v.y = 0.5f*v.y*(1.0f + erff(v.y*0.70710678118654752f));
            v.z = 0.5f*v.z*(1.0f + erff(v.z*0.70710678118654752f));
            v.w = 0.5f*v.w*(1.0f + erff(v.w*0.70710678118654752f));
        }
        size_t co = ((size_t)b*Cstride + rowoff + t)*(size_t)N + n0 + tx*4;
        if (resid) {
            float4 r = *reinterpret_cast<const float4*>(&resid[co]);
            v.x+=r.x; v.y+=r.y; v.z+=r.z; v.w+=r.w;
        }
        if (posadd) {
            float4 p = *reinterpret_cast<const float4*>(&posadd[(size_t)(rowoff+t)*N + n0 + tx*4]);
            v.x+=p.x; v.y+=p.y; v.z+=p.z; v.w+=p.w;
        }
        *reinterpret_cast<float4*>(&C[co]) = v;
    }
}

// ---------------- K transpose + V norms fused ----------------
__global__ void __launch_bounds__(256) transp_k() {
    int T = g_T;
    int t0 = blockIdx.x * 32;
    if (t0 >= T) return;
    int bh = blockIdx.y;
    int b = bh / Hh, h = bh % Hh;
    int tid = threadIdx.x;
    __shared__ float tile[64][33];

    const float* base = g_qkv + (size_t)b*TMAX*QKVW + Dd + h*HD;
#pragma unroll
    for (int i = 0; i < 8; i++) {
        int idx = i*256 + tid;
        int r = idx >> 6, c = idx & 63;
        int t = t0 + r;
        float v = (t < T) ? base[(size_t)t*QKVW + c] : 0.f;
        tile[c][r] = v;
    }
    __syncthreads();
    float* kout = g_ktr + (size_t)bh*HD*KTS;
#pragma unroll
    for (int i = 0; i < 8; i++) {
        int idx = i*256 + tid;
        int dd = idx >> 5, tt = idx & 31;
        kout[(size_t)dd*KTS + t0 + tt] = tile[dd][tt];
    }

    // fused V norms: 8 warps x 4 tokens each
    int w = tid >> 5, lane = tid & 31;
    const float* vbase = g_qkv + (size_t)b*TMAX*QKVW + 2*Dd + h*HD;
#pragma unroll
    for (int j = 0; j < 4; j++) {
        int t = t0 + w*4 + j;
        if (t < T) {
            const float* v = vbase + (size_t)t*QKVW;
            float s = v[lane]*v[lane] + v[lane+32]*v[lane+32];
#pragma unroll
            for (int o=16;o;o>>=1) s += __shfl_xor_sync(0xffffffffu, s, o);
            if (!lane) g_vnorm[bh*TMAX + t] = sqrtf(s);
        }
    }
}

// ---------------- layernorm: warp per row ----------------
__global__ void ln_k(const float* __restrict__ in, float* __restrict__ out,
                     const float* __restrict__ sc, const float* __restrict__ bi,
                     int inStride, int outStride, int fixedT)
{
    int T = fixedT ? fixedT : g_T;
    int lane = threadIdx.x & 31, w = threadIdx.x >> 5;
    int t = blockIdx.x*4 + w;
    if (t >= T) return;
    int b = blockIdx.y;
    const float4* row = reinterpret_cast<const float4*>(in + ((size_t)b*inStride + t)*Dd);
    float4 v0=row[lane], v1=row[lane+32], v2=row[lane+64];
    float s = v0.x+v0.y+v0.z+v0.w + v1.x+v1.y+v1.z+v1.w + v2.x+v2.y+v2.z+v2.w;
#pragma unroll
    for (int o=16;o;o>>=1) s += __shfl_xor_sync(0xffffffffu, s, o);
    float mean = s*(1.0f/Dd);
    float4 d0,d1,d2;
    d0.x=v0.x-mean; d0.y=v0.y-mean; d0.z=v0.z-mean; d0.w=v0.w-mean;
    d1.x=v1.x-mean; d1.y=v1.y-mean; d1.z=v1.z-mean; d1.w=v1.w-mean;
    d2.x=v2.x-mean; d2.y=v2.y-mean; d2.z=v2.z-mean; d2.w=v2.w-mean;
    float q = d0.x*d0.x+d0.y*d0.y+d0.z*d0.z+d0.w*d0.w
            + d1.x*d1.x+d1.y*d1.y+d1.z*d1.z+d1.w*d1.w
            + d2.x*d2.x+d2.y*d2.y+d2.z*d2.z+d2.w*d2.w;
#pragma unroll
    for (int o=16;o;o>>=1) q += __shfl_xor_sync(0xffffffffu, q, o);
    float inv = 1.0f/sqrtf(q*(1.0f/Dd) + LN_EPSc);
    const float4* sc4 = reinterpret_cast<const float4*>(sc);
    const float4* bi4 = reinterpret_cast<const float4*>(bi);
    float4* orow = reinterpret_cast<float4*>(out + ((size_t)b*outStride + t)*Dd);
    float4 s0=sc4[lane], s1=sc4[lane+32], s2=sc4[lane+64];
    float4 b0=bi4[lane], b1=bi4[lane+32], b2=bi4[lane+64];
    float4 o0,o1,o2;
    o0.x=d0.x*inv*s0.x+b0.x; o0.y=d0.y*inv*s0.y+b0.y; o0.z=d0.z*inv*s0.z+b0.z; o0.w=d0.w*inv*s0.w+b0.w;
    o1.x=d1.x*inv*s1.x+b1.x; o1.y=d1.y*inv*s1.y+b1.y; o1.z=d1.z*inv*s1.z+b1.z; o1.w=d1.w*inv*s1.w+b1.w;
    o2.x=d2.x*inv*s2.x+b2.x; o2.y=d2.y*inv*s2.y+b2.y; o2.z=d2.z*inv*s2.z+b2.z; o2.w=d2.w*inv*s2.w+b2.w;
    orow[lane]=o0; orow[lane+32]=o1; orow[lane+64]=o2;
}

// ---------------- attention: 8 queries per block, 256 threads ----------------
// scores: 2 keys per thread via float2 K^T loads (per-key d-order unchanged)
__global__ void __launch_bounds__(256) attn_k() {
    int T = g_T;
    int q0 = blockIdx.x * 8;
    if (q0 >= T) return;
    int bh = blockIdx.y;
    int b = bh / Hh, h = bh % Hh;
    int tid = threadIdx.x;

    __shared__ float sqT[HD][8];
    __shared__ float sc[8][TMAX];
    __shared__ float redsm[16][64];

    const float* base = g_qkv + (size_t)b*TMAX*QKVW;

    // load 8 q rows transposed: sqT[d][q]
    for (int e = tid; e < 8*HD; e += 256) {
        int q = e >> 6, d = e & 63;
        float v = 0.f;
        if (q0+q < T) v = base[(size_t)(q0+q)*QKVW + h*HD + d];
        sqT[d][q] = v;
    }
    __syncthreads();

    // scores: 2 keys per thread, coalesced float2 K^T reads
    const float* kt = g_ktr + (size_t)bh*HD*KTS;
    for (int k = tid*2; k < T; k += 512) {
        float a0[8] = {0.f,0.f,0.f,0.f,0.f,0.f,0.f,0.f};
        float a1[8] = {0.f,0.f,0.f,0.f,0.f,0.f,0.f,0.f};
        const float* kp = kt + k;
#pragma unroll 8
        for (int d = 0; d < HD; d++) {
            float2 kv = *reinterpret_cast<const float2*>(kp + (size_t)d*KTS);
            float4 qa = *reinterpret_cast<const float4*>(&sqT[d][0]);
            float4 qb = *reinterpret_cast<const float4*>(&sqT[d][4]);
            a0[0] += kv.x*qa.x; a0[1] += kv.x*qa.y; a0[2] += kv.x*qa.z; a0[3] += kv.x*qa.w;
            a0[4] += kv.x*qb.x; a0[5] += kv.x*qb.y; a0[6] += kv.x*qb.z; a0[7] += kv.x*qb.w;
            a1[0] += kv.y*qa.x; a1[1] += kv.y*qa.y; a1[2] += kv.y*qa.z; a1[3] += kv.y*qa.w;
            a1[4] += kv.y*qb.x; a1[5] += kv.y*qb.y; a1[6] += kv.y*qb.z; a1[7] += kv.y*qb.w;
        }
#pragma unroll
        for (int q = 0; q < 8; q++) sc[q][k] = a0[q]*0.125f;
        if (k + 1 < T) {
#pragma unroll
            for (int q = 0; q < 8; q++) sc[q][k+1] = a1[q]*0.125f;
        }
    }
    __syncthreads();

    // softmax: warp w handles query q0+w
    {
        int w = tid >> 5, lane = tid & 31;
        float m = -3.4e38f;
        for (int k=lane; k<T; k+=32) m = fmaxf(m, sc[w][k]);
#pragma unroll
        for (int o=16;o;o>>=1) m = fmaxf(m, __shfl_xor_sync(0xffffffffu, m, o));
        float s = 0.f;
        for (int k=lane; k<T; k+=32) { float e = expf(sc[w][k]-m); sc[w][k]=e; s+=e; }
#pragma unroll
        for (int o=16;o;o>>=1) s += __shfl_xor_sync(0xffffffffu, s, o);
        float inv = 1.0f/s;
        bool is_cls = (q0 + w == 0);
        for (int k=lane; k<T; k+=32) {
            float p = sc[w][k]*inv; sc[w][k]=p;
            if (is_cls) g_attn_cls[bh*TMAX + k] = p;
        }
    }
    __syncthreads();

    // AV: 16 segments x 16 d-groups
    int seg = tid >> 4, d4 = tid & 15;
    float4 a[8];
#pragma unroll
    for (int q=0;q<8;q++) a[q] = make_float4(0.f,0.f,0.f,0.f);
    for (int k = seg; k < T; k += 16) {
        float4 vv = *reinterpret_cast<const float4*>(base + (size_t)k*QKVW + 2*Dd + h*HD + d4*4);
#pragma unroll
        for (int q=0;q<8;q++) {
            float p = sc[q][k];
            a[q].x += p*vv.x; a[q].y += p*vv.y; a[q].z += p*vv.z; a[q].w += p*vv.w;
        }
    }
#pragma unroll
    for (int q=0;q<8;q++) {
        *reinterpret_cast<float4*>(&redsm[seg][d4*4]) = a[q];
        __syncthreads();
        if (tid < 64 && q0+q < T) {
            float s = 0.f;
#pragma unroll
            for (int sgi=0;sgi<16;sgi++) s += redsm[sgi][tid];
            g_ao[((size_t)b*TMAX + q0+q)*Dd + h*HD + tid] = s;
        }
        __syncthreads();
    }
}

// ---------------- per-batch stats ----------------
__global__ void stats_k() {
    int b = blockIdx.x, tid = threadIdx.x, T = g_T;
    __shared__ float red[256];
    for (int h = 0; h < Hh; h++) {
        float s = 0.f;
        for (int t = tid; t < T; t += 256) {
            float c = g_attn_cls[(b*Hh+h)*TMAX + t];
            s += c*logf(c + EPSc);
        }
        red[tid]=s; __syncthreads();
        for (int o=128;o;o>>=1){ if(tid<o) red[tid]+=red[tid+o]; __syncthreads(); }
        if (!tid) g_ent[b*Hh+h] = -red[0];
        __syncthreads();
    }
    int N = T-1;
    float loc = 0.f;
    for (int t=tid; t<N; t+=256) {
        float r = 0.f;
#pragma unroll
        for (int h=0;h<Hh;h++) {
            int o = (b*Hh+h)*TMAX + t+1;
            r += g_attn_cls[o]*g_vnorm[o];
        }
        g_raw[b*TMAX+t] = r; loc += r;
    }
    red[tid]=loc; __syncthreads();
    for (int o=128;o;o>>=1){ if(tid<o) red[tid]+=red[tid+o]; __syncthreads(); }
    if (!tid) g_mass[b] = red[0];
}

// ---------------- scores + decision + top-k selection ----------------
__global__ void keepsel_k() {
    int tid = threadIdx.x;
    int T = g_T, N = T-1;
    __shared__ float ssc[NMAX];
    __shared__ int sh_prune, sh_Nn;
    if (tid < N) {
        float s = 0.f;
#pragma unroll
        for (int b=0;b<Bz;b++) s += g_raw[b*TMAX+tid]/(g_mass[b]+EPSc);
        float sm = s*(1.0f/Bz);
        ssc[tid] = sm;
        g_scores[tid] = sm;
    }
    if (tid == 0) {
        int Nn = N, prune = 0;
        if (N > MIN_TOK) {
            float logT = logf((float)T);
            float rho_sum = 0.f;
            for (int b=0;b<Bz;b++) {
                float rb = 0.f;
                for (int h=0;h<Hh;h++) rb += g_ent[b*Hh+h]/logT;
                rho_sum += rb/(float)Hh;
            }
            float rho_mean = rho_sum/(float)Bz;
            if (g_prev_valid) {
                float ds = 0.f;
                for (int b=0;b<Bz;b++) ds += fabsf(g_mass[b]-g_prevmass[b])/(g_prevmass[b]+EPSc);
                float dm = ds/(float)Bz;
                float kr = 1.0f - GAMMAc*(rho_mean + dm);
                kr = fminf(fmaxf(kr, 0.0f), 1.0f);
                int cand = (int)((double)N*(double)kr);
                Nn = cand > MIN_TOK ? cand : MIN_TOK;
                if (Nn > N) Nn = N;
            }
            prune = (Nn < N) ? 1 : 0;
            for (int b=0;b<Bz;b++) g_prevmass[b] = g_mass[b];
            g_prev_valid = 1;
        }
        sh_prune = prune; sh_Nn = Nn;
        g_Tnew = Nn + 1;
    }
    __syncthreads();
    if (!sh_prune) {
        if (tid < T) g_keep[tid] = tid;
        return;
    }
    int Nn = sh_Nn;
    __shared__ unsigned char kept[NMAX];
    int isk = 0;
    if (tid < N) {
        float my = ssc[tid];
        int rank = 0;
        for (int j=0;j<N;j++) {
            float s = ssc[j];
            rank += (s > my) || (s == my && j < tid);
        }
        isk = (rank < Nn);
    }
    if (tid < NMAX) kept[tid] = (tid < N) ? (unsigned char)isk : 0;
    __syncthreads();
    if (tid < N && isk) {
        int pos = 1;
        for (int j=0;j<tid;j++) pos += kept[j];
        g_keep[pos] = tid + 1;
    }
    if (tid == 0) g_keep[0] = 0;
}

// ---------------- gather ----------------
__global__ void gather_k(const float* __restrict__ src, float* __restrict__ dst) {
    int pos = blockIdx.x;
    if (pos >= g_Tnew) return;
    int b = blockIdx.y;
    int s = g_keep[pos];
    const float4* sp = reinterpret_cast<const float4*>(src + ((size_t)b*TMAX + s)*Dd);
    float4* dp = reinterpret_cast<float4*>(dst + ((size_t)b*TMAX + pos)*Dd);
    if (threadIdx.x < 96) dp[threadIdx.x] = sp[threadIdx.x];
    if (pos==0 && b==0 && threadIdx.x==0) g_T = g_Tnew;
}

// ---------------- classifier head ----------------
__global__ void head_k(const float* __restrict__ hw, const float* __restrict__ hb,
                       float* __restrict__ out) {
    int b = blockIdx.y;
    __shared__ float xf[Dd];
    int tid = threadIdx.x;
    for (int d=tid; d<Dd; d+=256) xf[d] = g_cls[b*Dd+d];
    __syncthreads();
    int n = blockIdx.x*256 + tid;
    if (n < NCLSc) {
        float acc = hb[n];
        for (int k=0;k<Dd;k++) acc += xf[k]*hw[(size_t)k*NCLSc + n];
        out[(size_t)b*NCLSc + n] = acc;
    }
}

// ---------------- launch sequence ----------------
extern "C" void kernel_launch(void* const* d_in, const int* in_sizes, int n_in,
                              void* d_out, int out_size) {
    (void)in_sizes; (void)n_in; (void)out_size;
    const float* x        = (const float*)d_in[0];
    const float* patch_w  = (const float*)d_in[1];
    const float* patch_b  = (const float*)d_in[2];
    const float* cls_tok  = (const float*)d_in[3];
    const float* pos      = (const float*)d_in[4];
    const float* ln1_s    = (const float*)d_in[5];
    const float* ln1_b    = (const float*)d_in[6];
    const float* qkv_w    = (const float*)d_in[7];
    const float* qkv_b    = (const float*)d_in[8];
    const float* proj_w   = (const float*)d_in[9];
    const float* proj_b   = (const float*)d_in[10];
    const float* ln2_s    = (const float*)d_in[11];
    const float* ln2_b    = (const float*)d_in[12];
    const float* fc1_w    = (const float*)d_in[13];
    const float* fc1_b    = (const float*)d_in[14];
    const float* fc2_w    = (const float*)d_in[15];
    const float* fc2_b    = (const float*)d_in[16];
    const float* norm_s   = (const float*)d_in[17];
    const float* norm_b   = (const float*)d_in[18];
    const float* head_w   = (const float*)d_in[19];
    const float* head_b   = (const float*)d_in[20];
    float* out = (float*)d_out;

    float *pX,*pX2,*pXn,*pAo,*pQkv,*pH1,*pPat,*pCls;
    cudaGetSymbolAddress((void**)&pX,   g_x);
    cudaGetSymbolAddress((void**)&pX2,  g_x2);
    cudaGetSymbolAddress((void**)&pXn,  g_xn);
    cudaGetSymbolAddress((void**)&pAo,  g_ao);
    cudaGetSymbolAddress((void**)&pQkv, g_qkv);
    cudaGetSymbolAddress((void**)&pH1,  g_h1);
    cudaGetSymbolAddress((void**)&pPat, g_patches);
    cudaGetSymbolAddress((void**)&pCls, g_cls);

    init_k<<<Bz, Dd>>>(cls_tok, pos);
    {
        int tot = Bz*NMAX*Cc*Pp*Pp;
        patchify_k<<<(tot+255)/256, 256>>>(x);
    }
    gemm_k<<<dim3(9,6,Bz), 128>>>(pPat, patch_w, patch_b, pX, nullptr, pos,
                                  Cc*Pp*Pp, Dd, NMAX, TMAX, 1, NMAX, 0);

    float* bufs[2] = {pX, pX2};
    for (int l=0; l<Ll; l++) {
        float* cur = bufs[l & 1];
        float* nxt = bufs[(l+1) & 1];
        ln_k<<<dim3((TMAX+3)/4,Bz),128>>>(cur, pXn, ln1_s+l*Dd, ln1_b+l*Dd, TMAX, TMAX, 0);
        gemm_k<<<dim3(10,18,Bz), 128>>>(pXn, qkv_w + (size_t)l*Dd*QKVW, qkv_b + (size_t)l*QKVW,
                                        pQkv, nullptr, nullptr, Dd, QKVW, TMAX, TMAX, 0, 0, 0);
        transp_k<<<dim3((TMAX+31)/32, Bz*Hh), 256>>>();
        attn_k<<<dim3((TMAX+7)/8, Bz*Hh), 256>>>();
        gemm_k<<<dim3(10,6,Bz), 128>>>(pAo, proj_w + (size_t)l*Dd*Dd, proj_b + (size_t)l*Dd,
                                       cur, cur, nullptr, Dd, Dd, TMAX, TMAX, 0, 0, 0);
        ln_k<<<dim3((TMAX+3)/4,Bz),128>>>(cur, pXn, ln2_s+l*Dd, ln2_b+l*Dd, TMAX, TMAX, 0);
        gemm_k<<<dim3(10,24,Bz), 128>>>(pXn, fc1_w + (size_t)l*Dd*MLPd, fc1_b + (size_t)l*MLPd,
                                        pH1, nullptr, nullptr, Dd, MLPd, TMAX, TMAX, 0, 0, 1);
        gemm_k<<<dim3(10,6,Bz), 128>>>(pH1, fc2_w + (size_t)l*MLPd*Dd, fc2_b + (size_t)l*Dd,
                                       cur, cur, nullptr, MLPd, Dd, TMAX, TMAX, 0, 0, 0);
        stats_k<<<Bz, 256>>>();
        keepsel_k<<<1, 608>>>();
        gather_k<<<dim3(TMAX,Bz),128>>>(cur, nxt);
    }

    ln_k<<<dim3(1,Bz),128>>>(bufs[0], pCls, norm_s, norm_b, TMAX, 1, 1);
    head_k<<<dim3(4,Bz),256>>>(head_w, head_b, out);
}